// round 4
// baseline (speedup 1.0000x reference)
#include <cuda_runtime.h>
#include <stdint.h>

#define BNUM 32
#define PNUM 8732
#define CFG  20
#define NPAIR (BNUM*CFG)
#define KPRE 256
#define TOPK 200
#define CAP  2048
#define QCAP 1024
#define NT   512

typedef unsigned long long u64;

// ------------------------------------------------------------------
__device__ uint32_t g_keys[(size_t)NPAIR * PNUM];   // mono(prob) per [b][c][p]
__device__ float4   g_boxes[(size_t)BNUM * PNUM];   // decoded corner boxes

__device__ __forceinline__ uint32_t mono(float f) {
    uint32_t u = __float_as_uint(f);
    return (u & 0x80000000u) ? ~u : (u | 0x80000000u);
}
__device__ __forceinline__ float unmono(uint32_t k) {
    uint32_t u = (k & 0x80000000u) ? (k ^ 0x80000000u) : ~k;
    return __uint_as_float(u);
}

// ------------------------------------------------------------------
// kernel 1: softmax (exact jax.nn.softmax order) + decode
// ------------------------------------------------------------------
__global__ void prep_kernel(const float* __restrict__ loc,
                            const float* __restrict__ conf,
                            const float* __restrict__ prior) {
    int g = blockIdx.x * blockDim.x + threadIdx.x;
    if (g >= BNUM * PNUM) return;
    int b = g / PNUM, p = g % PNUM;

    const float* cp = conf + (size_t)g * 21;
    float x[21];
#pragma unroll
    for (int c = 0; c < 21; c++) x[c] = cp[c];
    float m = x[0];
#pragma unroll
    for (int c = 1; c < 21; c++) m = fmaxf(m, x[c]);
    float e[21];
    float s = 0.f;
#pragma unroll
    for (int c = 0; c < 21; c++) { e[c] = expf(x[c] - m); s += e[c]; }
#pragma unroll
    for (int c = 1; c < 21; c++)
        g_keys[((size_t)b * CFG + (c - 1)) * PNUM + p] = mono(e[c] / s);

    float4 l  = ((const float4*)loc)[g];
    float4 pr = ((const float4*)prior)[p];
    float cx = pr.x + (l.x * 0.1f) * pr.z;
    float cy = pr.y + (l.y * 0.1f) * pr.w;
    float w  = pr.z * expf(l.z * 0.2f);
    float h  = pr.w * expf(l.w * 0.2f);
    float x1 = cx - w * 0.5f;
    float y1 = cy - h * 0.5f;
    g_boxes[g] = make_float4(x1, y1, x1 + w, y1 + h);
}

// ------------------------------------------------------------------
// kernel 2: per (b,c) pair — 512 threads
// ------------------------------------------------------------------
__global__ __launch_bounds__(NT) void topk_nms_kernel(float* __restrict__ out) {
    __shared__ u64                s_h64[1024];     // hist (2048 u32) / compacted cands / supp matrix
    __shared__ uint32_t           s_csum[256];
    __shared__ u64                s_cand[CAP];
    __shared__ u64                s_key[KPRE];
    __shared__ float4             s_box[KPRE];
    __shared__ float              s_area[KPRE];
    __shared__ uint32_t           s_keep[8];
    __shared__ uint32_t           s_wpre[8];
    __shared__ uint32_t           s_sel[2];
    __shared__ uint32_t           s_cnt;
    uint32_t* s_hist = (uint32_t*)s_h64;

    const int pair = blockIdx.x;
    const int b    = pair / CFG;
    const int tid  = threadIdx.x;
    const int wid  = tid >> 5, lane = tid & 31;
    const uint32_t* __restrict__ keys = g_keys + (size_t)pair * PNUM;
    const uint4* __restrict__ keys4 = (const uint4*)keys;
    const int N4 = PNUM / 4;  // 2183

    // ================= level-0 histogram (top 11 bits), vectorized =================
    for (int i = tid; i < 2048; i += NT) s_hist[i] = 0;
    __syncthreads();
    for (int p = tid; p < N4; p += NT) {
        uint4 k = keys4[p];
        atomicAdd(&s_hist[k.x >> 21], 1u);
        atomicAdd(&s_hist[k.y >> 21], 1u);
        atomicAdd(&s_hist[k.z >> 21], 1u);
        atomicAdd(&s_hist[k.w >> 21], 1u);
    }
    __syncthreads();
    if (tid < 256) {
        uint32_t cs = 0;
#pragma unroll
        for (int i = 0; i < 8; i++) cs += s_hist[tid * 8 + i];
        s_csum[tid] = cs;
    }
    __syncthreads();
    if (tid == 0) {
        uint32_t acc = 0; int chunk = 0;
        for (int cg = 255; cg >= 0; cg--) {
            if (acc + s_csum[cg] >= KPRE) { chunk = cg; break; }
            acc += s_csum[cg];
        }
        int bb = chunk * 8;
        for (int bi = chunk * 8 + 7; bi >= chunk * 8; bi--) {
            if (acc + s_hist[bi] >= KPRE) { bb = bi; break; }
            acc += s_hist[bi];
        }
        s_sel[0] = (uint32_t)bb; s_sel[1] = acc;
    }
    __syncthreads();
    uint32_t pref = s_sel[0], n_above = s_sel[1];   // prefix = 11 bits
    uint32_t prefLen = 11;

    // ================= gather: key>>21 >= pref =================
    if (tid == 0) s_cnt = 0;
    __syncthreads();
#define TRYPUSH(kk, pp) \
    if (((kk) >> 21) >= pref) { \
        uint32_t pos = atomicAdd(&s_cnt, 1u); \
        if (pos < CAP) s_cand[pos] = ((u64)(kk) << 32) | (uint32_t)(~(uint32_t)(pp)); }
    for (int p = tid; p < N4; p += NT) {
        uint4 k = keys4[p];
        int p0 = 4 * p;
        TRYPUSH(k.x, p0);
        TRYPUSH(k.y, p0 + 1);
        TRYPUSH(k.z, p0 + 2);
        TRYPUSH(k.w, p0 + 3);
    }
#undef TRYPUSH
    __syncthreads();
    uint32_t M = s_cnt;

    // ---------- fallback (never taken for this data): refine globally at 21 bits ----------
    if (M > CAP) {
        for (int i = tid; i < 2048; i += NT) s_hist[i] = 0;
        __syncthreads();
        for (int p = tid; p < PNUM; p += NT) {
            uint32_t k = keys[p];
            if ((k >> 21) == pref) atomicAdd(&s_hist[(k >> 10) & 0x7FFu], 1u);
        }
        __syncthreads();
        if (tid < 256) {
            uint32_t cs = 0;
#pragma unroll
            for (int i = 0; i < 8; i++) cs += s_hist[tid * 8 + i];
            s_csum[tid] = cs;
        }
        __syncthreads();
        if (tid == 0) {
            uint32_t acc = n_above; int chunk = 0;
            for (int cg = 255; cg >= 0; cg--) {
                if (acc + s_csum[cg] >= KPRE) { chunk = cg; break; }
                acc += s_csum[cg];
            }
            int bb = chunk * 8;
            for (int bi = chunk * 8 + 7; bi >= chunk * 8; bi--) {
                if (acc + s_hist[bi] >= KPRE) { bb = bi; break; }
                acc += s_hist[bi];
            }
            s_sel[0] = (uint32_t)bb; s_sel[1] = acc;
        }
        __syncthreads();
        pref = (pref << 11) | s_sel[0]; n_above = s_sel[1]; prefLen = 21;
        if (tid == 0) s_cnt = 0;
        __syncthreads();
        for (int p = tid; p < PNUM; p += NT) {
            uint32_t k = keys[p];
            if ((k >> 10) >= pref) {
                uint32_t pos = atomicAdd(&s_cnt, 1u);
                if (pos < CAP) s_cand[pos] = ((u64)k << 32) | (uint32_t)(~(uint32_t)p);
            }
        }
        __syncthreads();
        M = s_cnt;
        if (M > CAP) M = CAP;
    }

    // ================= in-shared refine to exact 32-bit threshold F =================
    if (prefLen == 11) {   // refine bits [20:10]
        for (int i = tid; i < 2048; i += NT) s_hist[i] = 0;
        __syncthreads();
        for (uint32_t i = tid; i < M; i += NT) {
            uint32_t k = (uint32_t)(s_cand[i] >> 32);
            if ((k >> 21) == pref) atomicAdd(&s_hist[(k >> 10) & 0x7FFu], 1u);
        }
        __syncthreads();
        if (tid < 256) {
            uint32_t cs = 0;
#pragma unroll
            for (int i = 0; i < 8; i++) cs += s_hist[tid * 8 + i];
            s_csum[tid] = cs;
        }
        __syncthreads();
        if (tid == 0) {
            uint32_t acc = n_above; int chunk = 0;
            for (int cg = 255; cg >= 0; cg--) {
                if (acc + s_csum[cg] >= KPRE) { chunk = cg; break; }
                acc += s_csum[cg];
            }
            int bb = chunk * 8;
            for (int bi = chunk * 8 + 7; bi >= chunk * 8; bi--) {
                if (acc + s_hist[bi] >= KPRE) { bb = bi; break; }
                acc += s_hist[bi];
            }
            s_sel[0] = (uint32_t)bb; s_sel[1] = acc;
        }
        __syncthreads();
        pref = (pref << 11) | s_sel[0]; n_above = s_sel[1];
        __syncthreads();
    }
    // refine bits [9:0]
    {
        for (int i = tid; i < 2048; i += NT) s_hist[i] = 0;
        __syncthreads();
        for (uint32_t i = tid; i < M; i += NT) {
            uint32_t k = (uint32_t)(s_cand[i] >> 32);
            if ((k >> 10) == pref) atomicAdd(&s_hist[k & 0x3FFu], 1u);
        }
        __syncthreads();
        if (tid < 256) {
            uint32_t cs = 0;
#pragma unroll
            for (int i = 0; i < 8; i++) cs += s_hist[tid * 8 + i];
            s_csum[tid] = cs;
        }
        __syncthreads();
        if (tid == 0) {
            uint32_t acc = n_above; int chunk = 0;
            for (int cg = 255; cg >= 0; cg--) {
                if (acc + s_csum[cg] >= KPRE) { chunk = cg; break; }
                acc += s_csum[cg];
            }
            int bb = chunk * 8;
            for (int bi = chunk * 8 + 7; bi >= chunk * 8; bi--) {
                if (acc + s_hist[bi] >= KPRE) { bb = bi; break; }
                acc += s_hist[bi];
            }
            s_sel[0] = (uint32_t)bb;
        }
        __syncthreads();
    }
    uint32_t F = (pref << 10) | s_sel[0];

    // ================= compact qualifying (key >= F) into s_h64, rank-sort =================
    if (tid == 0) s_cnt = 0;
    __syncthreads();    // also retires last hist use of s_h64
    for (uint32_t i = tid; i < M; i += NT) {
        u64 c = s_cand[i];
        if ((uint32_t)(c >> 32) >= F) {
            uint32_t pos = atomicAdd(&s_cnt, 1u);
            if (pos < QCAP) s_h64[pos] = c;
        }
    }
    __syncthreads();
    uint32_t M2 = s_cnt; if (M2 > QCAP) M2 = QCAP;
    for (uint32_t i = tid; i < M2; i += NT) {
        u64 mine = s_h64[i];
        uint32_t rank = 0;
        for (uint32_t j = 0; j < M2; j++) rank += (s_h64[j] > mine);
        if (rank < KPRE) s_key[rank] = mine;
    }
    __syncthreads();

    // ================= extract top-256 (columns replicated across thread halves) ==========
    const int col = tid & 255;
    u64 key = s_key[col];
    uint32_t idx = ~(uint32_t)key;
    float scv = unmono((uint32_t)(key >> 32));
    float4 bj = g_boxes[(size_t)b * PNUM + idx];
    float aj = fmaxf(bj.z - bj.x, 0.f) * fmaxf(bj.w - bj.y, 0.f);
    if (tid < 256) {
        s_box[tid]  = bj;
        s_area[tid] = aj;
    }
    {
        bool valid = scv > 0.01f;
        uint32_t bal = __ballot_sync(0xFFFFFFFFu, valid);
        if (lane == 0 && wid < 8) s_keep[wid] = bal;
    }
    uint32_t* s_supp = (uint32_t*)s_h64;
    for (int i = tid; i < 2048; i += NT) s_supp[i] = 0;
    __syncthreads();

    // ============ suppression bitmatrix: 16 warps, col-group = wid&7, row parity = wid>>3 ==
    {
        const int cg    = wid & 7;
        const int par   = wid >> 3;          // 0: even rows, 1: odd rows
        const int imax  = cg * 32 + 32;      // rows that can suppress this col group
        for (int i = par; i < imax; i += 2) {
            float4 bi = s_box[i];
            float wx = fmaxf(fminf(bi.z, bj.z) - fmaxf(bi.x, bj.x), 0.f);
            float wy = fmaxf(fminf(bi.w, bj.w) - fmaxf(bi.y, bj.y), 0.f);
            float inter = __fmul_rn(wx, wy);
            float uni = __fadd_rn(__fadd_rn(s_area[i], aj), -inter);
            float ut = fmaxf(uni, 1e-9f);
            float r  = __fmul_rn(0.45f, ut);
            bool gt  = col > i;
            bool sup = gt && (inter > __fmul_rn(1.0001f, r));
            if (gt && !sup && inter >= __fmul_rn(0.9999f, r))
                sup = (inter / ut) > 0.45f;        // exact IEEE path, ~never taken
            uint32_t bal = __ballot_sync(0xFFFFFFFFu, sup);
            if (lane == 0) s_supp[i * 8 + cg] = bal;
        }
    }
    __syncthreads();

    // ================= serial greedy scan on warp 0 =================
    if (wid == 0) {
        uint32_t kw = (lane < 8) ? s_keep[lane] : 0u;
        for (int i = 0; i < KPRE - 1; i++) {
            uint32_t w = __shfl_sync(0xFFFFFFFFu, kw, i >> 5);
            if ((w >> (i & 31)) & 1u)
                kw &= ~s_supp[i * 8 + (lane & 7)];
        }
        if (lane < 8) s_keep[lane] = kw;
    }
    __syncthreads();

    // ================= compaction + output =================
    if (tid == 0) {
        uint32_t a = 0;
#pragma unroll
        for (int w2 = 0; w2 < 8; w2++) { s_wpre[w2] = a; a += __popc(s_keep[w2]); }
    }
    float* op = out + (size_t)pair * (TOPK * 5);
    for (int i = tid; i < TOPK * 5; i += NT) op[i] = 0.f;
    __syncthreads();

    if (tid < 256) {
        uint32_t kwm = s_keep[wid];
        if ((kwm >> lane) & 1u) {
            uint32_t rank = s_wpre[wid] + __popc(kwm & ((1u << lane) - 1u));
            if (rank < TOPK) {
                float* r = op + (size_t)rank * 5;
                r[0] = scv;
                r[1] = bj.x; r[2] = bj.y; r[3] = bj.z; r[4] = bj.w;
            }
        }
    }
}

// ------------------------------------------------------------------
extern "C" void kernel_launch(void* const* d_in, const int* in_sizes, int n_in,
                              void* d_out, int out_size) {
    const float* loc   = (const float*)d_in[0];
    const float* conf  = (const float*)d_in[1];
    const float* prior = (const float*)d_in[2];
    float* out = (float*)d_out;

    int total = BNUM * PNUM;
    prep_kernel<<<(total + 255) / 256, 256>>>(loc, conf, prior);
    topk_nms_kernel<<<NPAIR, NT>>>(out);
}

// round 5
// speedup vs baseline: 1.1805x; 1.1805x over previous
#include <cuda_runtime.h>
#include <stdint.h>

#define BNUM 32
#define PNUM 8732
#define CFG  20
#define NPAIR (BNUM*CFG)
#define KPRE 256
#define TOPK 200
#define CAP  2048
#define QCAP 1024
#define NT   256
#define TSAMP 128

typedef unsigned long long u64;

// ------------------------------------------------------------------
__device__ uint32_t g_keys[(size_t)NPAIR * PNUM];   // mono(prob) per [b][c][p]
__device__ float4   g_boxes[(size_t)BNUM * PNUM];   // decoded corner boxes

__device__ __forceinline__ uint32_t mono(float f) {
    uint32_t u = __float_as_uint(f);
    return (u & 0x80000000u) ? ~u : (u | 0x80000000u);
}
__device__ __forceinline__ float unmono(uint32_t k) {
    uint32_t u = (k & 0x80000000u) ? (k ^ 0x80000000u) : ~k;
    return __uint_as_float(u);
}

// ------------------------------------------------------------------
// kernel 1: softmax (exact jax.nn.softmax order) + decode
// ------------------------------------------------------------------
__global__ void prep_kernel(const float* __restrict__ loc,
                            const float* __restrict__ conf,
                            const float* __restrict__ prior) {
    int g = blockIdx.x * blockDim.x + threadIdx.x;
    if (g >= BNUM * PNUM) return;
    int b = g / PNUM, p = g % PNUM;

    const float* cp = conf + (size_t)g * 21;
    float x[21];
#pragma unroll
    for (int c = 0; c < 21; c++) x[c] = cp[c];
    float m = x[0];
#pragma unroll
    for (int c = 1; c < 21; c++) m = fmaxf(m, x[c]);
    float e[21];
    float s = 0.f;
#pragma unroll
    for (int c = 0; c < 21; c++) { e[c] = expf(x[c] - m); s += e[c]; }
#pragma unroll
    for (int c = 1; c < 21; c++)
        g_keys[((size_t)b * CFG + (c - 1)) * PNUM + p] = mono(e[c] / s);

    float4 l  = ((const float4*)loc)[g];
    float4 pr = ((const float4*)prior)[p];
    float cx = pr.x + (l.x * 0.1f) * pr.z;
    float cy = pr.y + (l.y * 0.1f) * pr.w;
    float w  = pr.z * expf(l.z * 0.2f);
    float h  = pr.w * expf(l.w * 0.2f);
    float x1 = cx - w * 0.5f;
    float y1 = cy - h * 0.5f;
    g_boxes[g] = make_float4(x1, y1, x1 + w, y1 + h);
}

// ------------------------------------------------------------------
// warp 0 helper: pick highest bin bb so that (#keys in bins > bb) + n0 < target
// <= (#keys in bins >= bb) + n0. Writes s_sel[0]=bb, s_sel[1]=count strictly above.
// Must be called by all 32 lanes of warp 0; s_csum[t] = sum of s_hist[8t..8t+7].
// ------------------------------------------------------------------
__device__ __forceinline__ void warp_select(const uint32_t* s_hist,
                                            const uint32_t* s_csum,
                                            uint32_t target, uint32_t n0,
                                            volatile uint32_t* s_sel) {
    const int l = threadIdx.x;   // lane (warp 0 only)
    uint32_t v[8]; uint32_t tot = 0;
#pragma unroll
    for (int m = 0; m < 8; m++) { v[m] = s_csum[l * 8 + m]; tot += v[m]; }
    uint32_t incl = tot;
#pragma unroll
    for (int o = 1; o < 32; o <<= 1) {
        uint32_t t = __shfl_down_sync(0xFFFFFFFFu, incl, o);
        if (l + o < 32) incl += t;
    }
    uint32_t above = incl - tot;     // sum of strictly-higher lanes
    bool here = (above + n0 < target) && (incl + n0 >= target);
    if (here) {
        uint32_t acc = above + n0;
        int mm = 0;
        for (int m = 7; m >= 0; m--) {
            if (acc + v[m] >= target) { mm = m; break; }
            acc += v[m];
        }
        int chunk = l * 8 + mm;
        int bb = chunk * 8;
        for (int bi = chunk * 8 + 7; bi >= chunk * 8; bi--) {
            uint32_t h = s_hist[bi];
            if (acc + h >= target) { bb = bi; break; }
            acc += h;
        }
        s_sel[0] = (uint32_t)bb; s_sel[1] = acc;
    }
}

// ------------------------------------------------------------------
// kernel 2: per (b,c) pair
// ------------------------------------------------------------------
__global__ __launch_bounds__(NT) void topk_nms_kernel(float* __restrict__ out) {
    __shared__ u64                s_h64[1024];     // hist(2048 u32) / compacted / supp matrix
    __shared__ uint32_t           s_csum[256];
    __shared__ u64                s_cand[CAP];
    __shared__ u64                s_key[KPRE];
    __shared__ float4             s_box[KPRE];
    __shared__ float              s_area[KPRE];
    __shared__ uint32_t           s_keep[8];
    __shared__ uint32_t           s_wpre[8];
    __shared__ uint32_t           s_sel[2];
    __shared__ uint32_t           s_cnt;
    uint32_t* s_hist = (uint32_t*)s_h64;

    const int pair = blockIdx.x;
    const int b    = pair / CFG;
    const int tid  = threadIdx.x;
    const int wid  = tid >> 5, lane = tid & 31;
    const uint32_t* __restrict__ keys = g_keys + (size_t)pair * PNUM;
    const uint4* __restrict__ keys4 = (const uint4*)keys;
    const int N4 = PNUM / 4;  // 2183

    // ================= sample histogram (25% stride sample, 2184 keys) =================
    for (int i = tid; i < 2048; i += NT) s_hist[i] = 0;
    __syncthreads();
    for (int i = tid; i < 546; i += NT) {
        uint4 k = keys4[i * 4];
        atomicAdd(&s_hist[k.x >> 21], 1u);
        atomicAdd(&s_hist[k.y >> 21], 1u);
        atomicAdd(&s_hist[k.z >> 21], 1u);
        atomicAdd(&s_hist[k.w >> 21], 1u);
    }
    __syncthreads();
    {
        uint32_t cs = 0;
#pragma unroll
        for (int i = 0; i < 8; i++) cs += s_hist[tid * 8 + i];
        s_csum[tid] = cs;
    }
    __syncthreads();
    if (wid == 0) warp_select(s_hist, s_csum, TSAMP, 0, s_sel);
    __syncthreads();
    uint32_t bb0 = s_sel[0];

    // ================= gather: key>>21 >= bb0 =================
    if (tid == 0) s_cnt = 0;
    __syncthreads();
#define TRYPUSH(kk, pp, TH) \
    if (((kk) >> 21) >= (TH)) { \
        uint32_t pos = atomicAdd(&s_cnt, 1u); \
        if (pos < CAP) s_cand[pos] = ((u64)(kk) << 32) | (uint32_t)(~(uint32_t)(pp)); }
    for (int p = tid; p < N4; p += NT) {
        uint4 k = keys4[p];
        int p0 = 4 * p;
        TRYPUSH(k.x, p0,     bb0);
        TRYPUSH(k.y, p0 + 1, bb0);
        TRYPUSH(k.z, p0 + 2, bb0);
        TRYPUSH(k.w, p0 + 3, bb0);
    }
    __syncthreads();
    uint32_t M = s_cnt;

    // ================= fallback: exact global select (rare) =================
    if (M < KPRE || M > CAP) {
        for (int i = tid; i < 2048; i += NT) s_hist[i] = 0;
        __syncthreads();
        for (int p = tid; p < N4; p += NT) {
            uint4 k = keys4[p];
            atomicAdd(&s_hist[k.x >> 21], 1u);
            atomicAdd(&s_hist[k.y >> 21], 1u);
            atomicAdd(&s_hist[k.z >> 21], 1u);
            atomicAdd(&s_hist[k.w >> 21], 1u);
        }
        __syncthreads();
        {
            uint32_t cs = 0;
#pragma unroll
            for (int i = 0; i < 8; i++) cs += s_hist[tid * 8 + i];
            s_csum[tid] = cs;
        }
        __syncthreads();
        if (wid == 0) warp_select(s_hist, s_csum, KPRE, 0, s_sel);
        __syncthreads();
        uint32_t bbe = s_sel[0], n_above = s_sel[1];
        if (tid == 0) s_cnt = 0;
        __syncthreads();
        for (int p = tid; p < N4; p += NT) {
            uint4 k = keys4[p];
            int p0 = 4 * p;
            TRYPUSH(k.x, p0,     bbe);
            TRYPUSH(k.y, p0 + 1, bbe);
            TRYPUSH(k.z, p0 + 2, bbe);
            TRYPUSH(k.w, p0 + 3, bbe);
        }
        __syncthreads();
        M = s_cnt;
        if (M > CAP) {   // boundary bin too fat: refine globally to 21 bits
            for (int i = tid; i < 2048; i += NT) s_hist[i] = 0;
            __syncthreads();
            for (int p = tid; p < PNUM; p += NT) {
                uint32_t k = keys[p];
                if ((k >> 21) == bbe) atomicAdd(&s_hist[(k >> 10) & 0x7FFu], 1u);
            }
            __syncthreads();
            {
                uint32_t cs = 0;
#pragma unroll
                for (int i = 0; i < 8; i++) cs += s_hist[tid * 8 + i];
                s_csum[tid] = cs;
            }
            __syncthreads();
            if (wid == 0) warp_select(s_hist, s_csum, KPRE, n_above, s_sel);
            __syncthreads();
            uint32_t pref21 = (bbe << 11) | s_sel[0];
            if (tid == 0) s_cnt = 0;
            __syncthreads();
            for (int p = tid; p < PNUM; p += NT) {
                uint32_t k = keys[p];
                if ((k >> 10) >= pref21) {
                    uint32_t pos = atomicAdd(&s_cnt, 1u);
                    if (pos < CAP) s_cand[pos] = ((u64)k << 32) | (uint32_t)(~(uint32_t)p);
                }
            }
            __syncthreads();
            M = s_cnt;
            if (M > CAP) M = CAP;   // pathological ties; superset property may degrade but deterministic
        }
    }
#undef TRYPUSH

    // ================= fresh 3-level in-shared refine -> exact F =================
    uint32_t pref = 0, n0 = 0;
    // level A: bits [31:21]
    for (int i = tid; i < 2048; i += NT) s_hist[i] = 0;
    __syncthreads();
    for (uint32_t i = tid; i < M; i += NT)
        atomicAdd(&s_hist[(uint32_t)(s_cand[i] >> 32) >> 21], 1u);
    __syncthreads();
    {
        uint32_t cs = 0;
#pragma unroll
        for (int i = 0; i < 8; i++) cs += s_hist[tid * 8 + i];
        s_csum[tid] = cs;
    }
    __syncthreads();
    if (wid == 0) warp_select(s_hist, s_csum, KPRE, 0, s_sel);
    __syncthreads();
    pref = s_sel[0]; n0 = s_sel[1];
    __syncthreads();
    // level B: bits [20:10]
    for (int i = tid; i < 2048; i += NT) s_hist[i] = 0;
    __syncthreads();
    for (uint32_t i = tid; i < M; i += NT) {
        uint32_t k = (uint32_t)(s_cand[i] >> 32);
        if ((k >> 21) == pref) atomicAdd(&s_hist[(k >> 10) & 0x7FFu], 1u);
    }
    __syncthreads();
    {
        uint32_t cs = 0;
#pragma unroll
        for (int i = 0; i < 8; i++) cs += s_hist[tid * 8 + i];
        s_csum[tid] = cs;
    }
    __syncthreads();
    if (wid == 0) warp_select(s_hist, s_csum, KPRE, n0, s_sel);
    __syncthreads();
    pref = (pref << 11) | s_sel[0]; n0 = s_sel[1];
    __syncthreads();
    // level C: bits [9:0]
    for (int i = tid; i < 2048; i += NT) s_hist[i] = 0;
    __syncthreads();
    for (uint32_t i = tid; i < M; i += NT) {
        uint32_t k = (uint32_t)(s_cand[i] >> 32);
        if ((k >> 10) == pref) atomicAdd(&s_hist[k & 0x3FFu], 1u);
    }
    __syncthreads();
    {
        uint32_t cs = 0;
#pragma unroll
        for (int i = 0; i < 8; i++) cs += s_hist[tid * 8 + i];
        s_csum[tid] = cs;
    }
    __syncthreads();
    if (wid == 0) warp_select(s_hist, s_csum, KPRE, n0, s_sel);
    __syncthreads();
    uint32_t F = (pref << 10) | s_sel[0];

    // ================= compact qualifying (key >= F) =================
    if (tid == 0) s_cnt = 0;
    __syncthreads();    // retires last hist use of s_h64
    for (uint32_t i = tid; i < M; i += NT) {
        u64 c = s_cand[i];
        if ((uint32_t)(c >> 32) >= F) {
            uint32_t pos = atomicAdd(&s_cnt, 1u);
            if (pos < QCAP) s_h64[pos] = c;
        }
    }
    __syncthreads();
    uint32_t M2 = s_cnt; if (M2 > QCAP) M2 = QCAP;

    // ================= sort: bitonic-256 (generic) or rank-sort (ties) =================
    if (M2 == KPRE) {
        u64 mine = s_h64[tid];
        __syncthreads();
#pragma unroll
        for (uint32_t k = 2; k <= 256; k <<= 1) {
            for (uint32_t j = k >> 1; j >= 1; j >>= 1) {
                u64 other;
                if (j >= 32) {
                    s_key[tid] = mine;
                    __syncthreads();
                    other = s_key[tid ^ j];
                    __syncthreads();
                } else {
                    other = __shfl_xor_sync(0xFFFFFFFFu, mine, j);
                }
                bool lower   = (tid & j) == 0;
                bool dirDesc = (tid & k) == 0;
                bool takeMax = (lower == dirDesc);
                u64 mx = mine > other ? mine : other;
                u64 mn = mine > other ? other : mine;
                mine = takeMax ? mx : mn;
            }
        }
        s_key[tid] = mine;
    } else {
        for (uint32_t i = tid; i < M2; i += NT) {
            u64 mine = s_h64[i];
            uint32_t rank = 0;
            for (uint32_t j = 0; j < M2; j++) rank += (s_h64[j] > mine);
            if (rank < KPRE) s_key[rank] = mine;
        }
    }
    __syncthreads();

    // ================= extract top-256 =================
    u64 key = s_key[tid];
    uint32_t idx = ~(uint32_t)key;
    float scv = unmono((uint32_t)(key >> 32));
    float4 bj = g_boxes[(size_t)b * PNUM + idx];
    float aj = fmaxf(bj.z - bj.x, 0.f) * fmaxf(bj.w - bj.y, 0.f);
    s_box[tid]  = bj;
    s_area[tid] = aj;
    {
        bool valid = scv > 0.01f;
        uint32_t bal = __ballot_sync(0xFFFFFFFFu, valid);
        if (lane == 0) s_keep[wid] = bal;
    }
    uint32_t* s_supp = (uint32_t*)s_h64;
    for (int i = tid; i < 2048; i += NT) s_supp[i] = 0;
    __syncthreads();

    // ================= suppression bitmatrix (warp-bounded rows, band-exact IoU) =========
    {
        const int imax = wid * 32 + 32;    // rows that can suppress this warp's columns
        for (int i = 0; i < imax; i++) {
            float4 bi = s_box[i];
            float wx = fmaxf(fminf(bi.z, bj.z) - fmaxf(bi.x, bj.x), 0.f);
            float wy = fmaxf(fminf(bi.w, bj.w) - fmaxf(bi.y, bj.y), 0.f);
            float inter = __fmul_rn(wx, wy);
            float uni = __fadd_rn(__fadd_rn(s_area[i], aj), -inter);
            float ut = fmaxf(uni, 1e-9f);
            float r  = __fmul_rn(0.45f, ut);
            bool gt  = tid > i;
            bool sup = gt && (inter > __fmul_rn(1.0001f, r));
            if (gt && !sup && inter >= __fmul_rn(0.9999f, r))
                sup = (inter / ut) > 0.45f;        // exact IEEE path, ~never taken
            uint32_t bal = __ballot_sync(0xFFFFFFFFu, sup);
            if (lane == 0) s_supp[i * 8 + wid] = bal;
        }
    }
    __syncthreads();

    // ================= serial greedy scan on warp 0 =================
    if (wid == 0) {
        uint32_t kw = (lane < 8) ? s_keep[lane] : 0u;
        for (int i = 0; i < KPRE - 1; i++) {
            uint32_t w = __shfl_sync(0xFFFFFFFFu, kw, i >> 5);
            if ((w >> (i & 31)) & 1u)
                kw &= ~s_supp[i * 8 + (lane & 7)];
        }
        if (lane < 8) s_keep[lane] = kw;
    }
    __syncthreads();

    // ================= compaction + output =================
    if (tid == 0) {
        uint32_t a = 0;
#pragma unroll
        for (int w2 = 0; w2 < 8; w2++) { s_wpre[w2] = a; a += __popc(s_keep[w2]); }
    }
    float* op = out + (size_t)pair * (TOPK * 5);
    for (int i = tid; i < TOPK * 5; i += NT) op[i] = 0.f;
    __syncthreads();

    uint32_t kwm = s_keep[wid];
    if ((kwm >> lane) & 1u) {
        uint32_t rank = s_wpre[wid] + __popc(kwm & ((1u << lane) - 1u));
        if (rank < TOPK) {
            float* r = op + (size_t)rank * 5;
            r[0] = scv;
            r[1] = bj.x; r[2] = bj.y; r[3] = bj.z; r[4] = bj.w;
        }
    }
}

// ------------------------------------------------------------------
extern "C" void kernel_launch(void* const* d_in, const int* in_sizes, int n_in,
                              void* d_out, int out_size) {
    const float* loc   = (const float*)d_in[0];
    const float* conf  = (const float*)d_in[1];
    const float* prior = (const float*)d_in[2];
    float* out = (float*)d_out;

    int total = BNUM * PNUM;
    prep_kernel<<<(total + 255) / 256, 256>>>(loc, conf, prior);
    topk_nms_kernel<<<NPAIR, NT>>>(out);
}

// round 6
// speedup vs baseline: 1.2979x; 1.0994x over previous
#include <cuda_runtime.h>
#include <stdint.h>

#define BNUM 32
#define PNUM 8732
#define CFG  20
#define NPAIR (BNUM*CFG)
#define KPRE 256
#define TOPK 200
#define CAP  2048
#define QCAP 1024
#define NT   256
#define TSAMP 128

typedef unsigned long long u64;

// ------------------------------------------------------------------
__device__ uint32_t g_keys[(size_t)NPAIR * PNUM];   // mono(prob) per [b][c][p]
__device__ float4   g_boxes[(size_t)BNUM * PNUM];   // decoded corner boxes

__device__ __forceinline__ uint32_t mono(float f) {
    uint32_t u = __float_as_uint(f);
    return (u & 0x80000000u) ? ~u : (u | 0x80000000u);
}
__device__ __forceinline__ float unmono(uint32_t k) {
    uint32_t u = (k & 0x80000000u) ? (k ^ 0x80000000u) : ~k;
    return __uint_as_float(u);
}

// ------------------------------------------------------------------
// kernel 1: softmax (exact jax.nn.softmax order) + decode
// ------------------------------------------------------------------
__global__ void prep_kernel(const float* __restrict__ loc,
                            const float* __restrict__ conf,
                            const float* __restrict__ prior) {
    int g = blockIdx.x * blockDim.x + threadIdx.x;
    if (g >= BNUM * PNUM) return;
    int b = g / PNUM, p = g % PNUM;

    const float* cp = conf + (size_t)g * 21;
    float x[21];
#pragma unroll
    for (int c = 0; c < 21; c++) x[c] = cp[c];
    float m = x[0];
#pragma unroll
    for (int c = 1; c < 21; c++) m = fmaxf(m, x[c]);
    float e[21];
    float s = 0.f;
#pragma unroll
    for (int c = 0; c < 21; c++) { e[c] = expf(x[c] - m); s += e[c]; }
#pragma unroll
    for (int c = 1; c < 21; c++)
        g_keys[((size_t)b * CFG + (c - 1)) * PNUM + p] = mono(e[c] / s);

    float4 l  = ((const float4*)loc)[g];
    float4 pr = ((const float4*)prior)[p];
    float cx = pr.x + (l.x * 0.1f) * pr.z;
    float cy = pr.y + (l.y * 0.1f) * pr.w;
    float w  = pr.z * expf(l.z * 0.2f);
    float h  = pr.w * expf(l.w * 0.2f);
    float x1 = cx - w * 0.5f;
    float y1 = cy - h * 0.5f;
    g_boxes[g] = make_float4(x1, y1, x1 + w, y1 + h);
}

// ------------------------------------------------------------------
// warp 0 helper: pick highest bin bb so that (#keys in bins > bb) + n0 < target
// <= (#keys in bins >= bb) + n0. Writes s_sel[0]=bb, s_sel[1]=count strictly above.
// ------------------------------------------------------------------
__device__ __forceinline__ void warp_select(const uint32_t* s_hist,
                                            const uint32_t* s_csum,
                                            uint32_t target, uint32_t n0,
                                            volatile uint32_t* s_sel) {
    const int l = threadIdx.x;   // lane (warp 0 only)
    uint32_t v[8]; uint32_t tot = 0;
#pragma unroll
    for (int m = 0; m < 8; m++) { v[m] = s_csum[l * 8 + m]; tot += v[m]; }
    uint32_t incl = tot;
#pragma unroll
    for (int o = 1; o < 32; o <<= 1) {
        uint32_t t = __shfl_down_sync(0xFFFFFFFFu, incl, o);
        if (l + o < 32) incl += t;
    }
    uint32_t above = incl - tot;     // sum of strictly-higher lanes
    bool here = (above + n0 < target) && (incl + n0 >= target);
    if (here) {
        uint32_t acc = above + n0;
        int mm = 0;
        for (int m = 7; m >= 0; m--) {
            if (acc + v[m] >= target) { mm = m; break; }
            acc += v[m];
        }
        int chunk = l * 8 + mm;
        int bb = chunk * 8;
        for (int bi = chunk * 8 + 7; bi >= chunk * 8; bi--) {
            uint32_t h = s_hist[bi];
            if (acc + h >= target) { bb = bi; break; }
            acc += h;
        }
        s_sel[0] = (uint32_t)bb; s_sel[1] = acc;
    }
}

// ------------------------------------------------------------------
// kernel 2: per (b,c) pair
// ------------------------------------------------------------------
__global__ __launch_bounds__(NT) void topk_nms_kernel(float* __restrict__ out) {
    __shared__ u64                s_h64[1024];     // hist(2048 u32) / compacted / supp matrix
    __shared__ uint32_t           s_csum[256];
    __shared__ u64                s_cand[CAP];
    __shared__ u64                s_key[KPRE];
    __shared__ float4             s_box[KPRE];
    __shared__ float              s_area[KPRE];
    __shared__ uint32_t           s_keep[8];
    __shared__ uint32_t           s_wpre[8];
    __shared__ uint32_t           s_sel[2];
    __shared__ uint32_t           s_cnt;
    uint32_t* s_hist = (uint32_t*)s_h64;

    const int pair = blockIdx.x;
    const int b    = pair / CFG;
    const int tid  = threadIdx.x;
    const int wid  = tid >> 5, lane = tid & 31;
    const uint32_t* __restrict__ keys = g_keys + (size_t)pair * PNUM;
    const uint4* __restrict__ keys4 = (const uint4*)keys;
    const int N4 = PNUM / 4;  // 2183

    // ================= sample histogram (25% stride sample, 2184 keys) =================
    for (int i = tid; i < 2048; i += NT) s_hist[i] = 0;
    __syncthreads();
    for (int i = tid; i < 546; i += NT) {
        uint4 k = keys4[i * 4];
        atomicAdd(&s_hist[k.x >> 21], 1u);
        atomicAdd(&s_hist[k.y >> 21], 1u);
        atomicAdd(&s_hist[k.z >> 21], 1u);
        atomicAdd(&s_hist[k.w >> 21], 1u);
    }
    __syncthreads();
    {
        uint32_t cs = 0;
#pragma unroll
        for (int i = 0; i < 8; i++) cs += s_hist[tid * 8 + i];
        s_csum[tid] = cs;
    }
    __syncthreads();
    if (wid == 0) warp_select(s_hist, s_csum, TSAMP, 0, s_sel);
    __syncthreads();
    uint32_t bb0 = s_sel[0];

    // ================= gather: key>>21 >= bb0 =================
    if (tid == 0) s_cnt = 0;
    __syncthreads();
#define TRYPUSH(kk, pp, TH) \
    if (((kk) >> 21) >= (TH)) { \
        uint32_t pos = atomicAdd(&s_cnt, 1u); \
        if (pos < CAP) s_cand[pos] = ((u64)(kk) << 32) | (uint32_t)(~(uint32_t)(pp)); }
    for (int p = tid; p < N4; p += NT) {
        uint4 k = keys4[p];
        int p0 = 4 * p;
        TRYPUSH(k.x, p0,     bb0);
        TRYPUSH(k.y, p0 + 1, bb0);
        TRYPUSH(k.z, p0 + 2, bb0);
        TRYPUSH(k.w, p0 + 3, bb0);
    }
    __syncthreads();
    uint32_t M = s_cnt;

    // ================= fallback: exact global select (rare) =================
    if (M < KPRE || M > CAP) {
        for (int i = tid; i < 2048; i += NT) s_hist[i] = 0;
        __syncthreads();
        for (int p = tid; p < N4; p += NT) {
            uint4 k = keys4[p];
            atomicAdd(&s_hist[k.x >> 21], 1u);
            atomicAdd(&s_hist[k.y >> 21], 1u);
            atomicAdd(&s_hist[k.z >> 21], 1u);
            atomicAdd(&s_hist[k.w >> 21], 1u);
        }
        __syncthreads();
        {
            uint32_t cs = 0;
#pragma unroll
            for (int i = 0; i < 8; i++) cs += s_hist[tid * 8 + i];
            s_csum[tid] = cs;
        }
        __syncthreads();
        if (wid == 0) warp_select(s_hist, s_csum, KPRE, 0, s_sel);
        __syncthreads();
        uint32_t bbe = s_sel[0], n_above = s_sel[1];
        if (tid == 0) s_cnt = 0;
        __syncthreads();
        for (int p = tid; p < N4; p += NT) {
            uint4 k = keys4[p];
            int p0 = 4 * p;
            TRYPUSH(k.x, p0,     bbe);
            TRYPUSH(k.y, p0 + 1, bbe);
            TRYPUSH(k.z, p0 + 2, bbe);
            TRYPUSH(k.w, p0 + 3, bbe);
        }
        __syncthreads();
        M = s_cnt;
        if (M > CAP) {   // boundary bin too fat: refine globally to 21 bits
            for (int i = tid; i < 2048; i += NT) s_hist[i] = 0;
            __syncthreads();
            for (int p = tid; p < PNUM; p += NT) {
                uint32_t k = keys[p];
                if ((k >> 21) == bbe) atomicAdd(&s_hist[(k >> 10) & 0x7FFu], 1u);
            }
            __syncthreads();
            {
                uint32_t cs = 0;
#pragma unroll
                for (int i = 0; i < 8; i++) cs += s_hist[tid * 8 + i];
                s_csum[tid] = cs;
            }
            __syncthreads();
            if (wid == 0) warp_select(s_hist, s_csum, KPRE, n_above, s_sel);
            __syncthreads();
            uint32_t pref21 = (bbe << 11) | s_sel[0];
            if (tid == 0) s_cnt = 0;
            __syncthreads();
            for (int p = tid; p < PNUM; p += NT) {
                uint32_t k = keys[p];
                if ((k >> 10) >= pref21) {
                    uint32_t pos = atomicAdd(&s_cnt, 1u);
                    if (pos < CAP) s_cand[pos] = ((u64)k << 32) | (uint32_t)(~(uint32_t)p);
                }
            }
            __syncthreads();
            M = s_cnt;
            if (M > CAP) M = CAP;
        }
    }
#undef TRYPUSH

    // ================= fresh 3-level in-shared refine -> exact F =================
    uint32_t pref = 0, n0 = 0;
    // level A: bits [31:21]
    for (int i = tid; i < 2048; i += NT) s_hist[i] = 0;
    __syncthreads();
    for (uint32_t i = tid; i < M; i += NT)
        atomicAdd(&s_hist[(uint32_t)(s_cand[i] >> 32) >> 21], 1u);
    __syncthreads();
    {
        uint32_t cs = 0;
#pragma unroll
        for (int i = 0; i < 8; i++) cs += s_hist[tid * 8 + i];
        s_csum[tid] = cs;
    }
    __syncthreads();
    if (wid == 0) warp_select(s_hist, s_csum, KPRE, 0, s_sel);
    __syncthreads();
    pref = s_sel[0]; n0 = s_sel[1];
    __syncthreads();
    // level B: bits [20:10]
    for (int i = tid; i < 2048; i += NT) s_hist[i] = 0;
    __syncthreads();
    for (uint32_t i = tid; i < M; i += NT) {
        uint32_t k = (uint32_t)(s_cand[i] >> 32);
        if ((k >> 21) == pref) atomicAdd(&s_hist[(k >> 10) & 0x7FFu], 1u);
    }
    __syncthreads();
    {
        uint32_t cs = 0;
#pragma unroll
        for (int i = 0; i < 8; i++) cs += s_hist[tid * 8 + i];
        s_csum[tid] = cs;
    }
    __syncthreads();
    if (wid == 0) warp_select(s_hist, s_csum, KPRE, n0, s_sel);
    __syncthreads();
    pref = (pref << 11) | s_sel[0]; n0 = s_sel[1];
    __syncthreads();
    // level C: bits [9:0]
    for (int i = tid; i < 2048; i += NT) s_hist[i] = 0;
    __syncthreads();
    for (uint32_t i = tid; i < M; i += NT) {
        uint32_t k = (uint32_t)(s_cand[i] >> 32);
        if ((k >> 10) == pref) atomicAdd(&s_hist[k & 0x3FFu], 1u);
    }
    __syncthreads();
    {
        uint32_t cs = 0;
#pragma unroll
        for (int i = 0; i < 8; i++) cs += s_hist[tid * 8 + i];
        s_csum[tid] = cs;
    }
    __syncthreads();
    if (wid == 0) warp_select(s_hist, s_csum, KPRE, n0, s_sel);
    __syncthreads();
    uint32_t F = (pref << 10) | s_sel[0];

    // ================= compact qualifying (key >= F) =================
    if (tid == 0) s_cnt = 0;
    __syncthreads();    // retires last hist use of s_h64
    for (uint32_t i = tid; i < M; i += NT) {
        u64 c = s_cand[i];
        if ((uint32_t)(c >> 32) >= F) {
            uint32_t pos = atomicAdd(&s_cnt, 1u);
            if (pos < QCAP) s_h64[pos] = c;
        }
    }
    __syncthreads();
    uint32_t M2 = s_cnt; if (M2 > QCAP) M2 = QCAP;

    // ================= sort: bitonic-256 (generic) or rank-sort (ties) =================
    if (M2 == KPRE) {
        u64 mine = s_h64[tid];
        __syncthreads();
#pragma unroll
        for (uint32_t k = 2; k <= 256; k <<= 1) {
            for (uint32_t j = k >> 1; j >= 1; j >>= 1) {
                u64 other;
                if (j >= 32) {
                    s_key[tid] = mine;
                    __syncthreads();
                    other = s_key[tid ^ j];
                    __syncthreads();
                } else {
                    other = __shfl_xor_sync(0xFFFFFFFFu, mine, j);
                }
                bool lower   = (tid & j) == 0;
                bool dirDesc = (tid & k) == 0;
                bool takeMax = (lower == dirDesc);
                u64 mx = mine > other ? mine : other;
                u64 mn = mine > other ? other : mine;
                mine = takeMax ? mx : mn;
            }
        }
        s_key[tid] = mine;
    } else {
        for (uint32_t i = tid; i < M2; i += NT) {
            u64 mine = s_h64[i];
            uint32_t rank = 0;
            for (uint32_t j = 0; j < M2; j++) rank += (s_h64[j] > mine);
            if (rank < KPRE) s_key[rank] = mine;
        }
    }
    __syncthreads();

    // ================= extract top-256 =================
    u64 key = s_key[tid];
    uint32_t idx = ~(uint32_t)key;
    float scv = unmono((uint32_t)(key >> 32));
    float4 bj = g_boxes[(size_t)b * PNUM + idx];
    float aj = fmaxf(bj.z - bj.x, 0.f) * fmaxf(bj.w - bj.y, 0.f);
    s_box[tid]  = bj;
    s_area[tid] = aj;
    {
        bool valid = scv > 0.01f;
        uint32_t bal = __ballot_sync(0xFFFFFFFFu, valid);
        if (lane == 0) s_keep[wid] = bal;
    }
    // hoist output zeroing: global stores drain while bitmatrix computes
    float* op = out + (size_t)pair * (TOPK * 5);
    for (int i = tid; i < TOPK * 5; i += NT) op[i] = 0.f;
    uint32_t* s_supp = (uint32_t*)s_h64;   // no zeroing needed: scan masks to written triangle
    __syncthreads();

    // ===== suppression bitmatrix: balanced schedule (each warp 144 rows total) =====
    // column-group g loop; rows strided by 8 warps within each group.
    for (int g = 0; g < 8; g++) {
        const int   colg = g * 32 + lane;
        const float4 bg  = s_box[colg];
        const float  ag  = s_area[colg];
        const int    imax = g * 32 + 32;
        for (int i = wid; i < imax; i += 8) {
            float4 bi = s_box[i];
            float wx = fmaxf(fminf(bi.z, bg.z) - fmaxf(bi.x, bg.x), 0.f);
            float wy = fmaxf(fminf(bi.w, bg.w) - fmaxf(bi.y, bg.y), 0.f);
            float inter = __fmul_rn(wx, wy);
            float uni = __fadd_rn(__fadd_rn(s_area[i], ag), -inter);
            float ut = fmaxf(uni, 1e-9f);
            float r  = __fmul_rn(0.45f, ut);
            bool gt  = colg > i;
            bool sup = gt && (inter > __fmul_rn(1.0001f, r));
            if (gt && !sup && inter >= __fmul_rn(0.9999f, r))
                sup = (inter / ut) > 0.45f;        // exact IEEE path, ~never taken
            uint32_t bal = __ballot_sync(0xFFFFFFFFu, sup);
            if (lane == 0) s_supp[i * 8 + g] = bal;
        }
    }
    __syncthreads();

    // ================= serial greedy scan on warp 0 (triangle-masked reads) =========
    if (wid == 0) {
        uint32_t kw = (lane < 8) ? s_keep[lane] : 0u;
        const int rowcap = lane * 32 + 31;   // word `lane` written only for rows i <= rowcap
        uint32_t nxt = (lane < 8) ? s_supp[0 * 8 + lane] : 0u;  // row 0 always <= rowcap for lane<8
        for (int i = 0; i < KPRE - 1; i++) {
            uint32_t cur = nxt;
            // prefetch row i+1's word (off the dependency chain)
            nxt = (lane < 8 && (i + 1) <= rowcap) ? s_supp[(i + 1) * 8 + lane] : 0u;
            uint32_t w = __shfl_sync(0xFFFFFFFFu, kw, i >> 5);
            if ((w >> (i & 31)) & 1u)
                kw &= ~cur;
        }
        if (lane < 8) s_keep[lane] = kw;
    }
    __syncthreads();

    // ================= compaction + output =================
    if (tid == 0) {
        uint32_t a = 0;
#pragma unroll
        for (int w2 = 0; w2 < 8; w2++) { s_wpre[w2] = a; a += __popc(s_keep[w2]); }
    }
    __syncthreads();

    uint32_t kwm = s_keep[wid];
    if ((kwm >> lane) & 1u) {
        uint32_t rank = s_wpre[wid] + __popc(kwm & ((1u << lane) - 1u));
        if (rank < TOPK) {
            float* r = op + (size_t)rank * 5;
            r[0] = scv;
            r[1] = bj.x; r[2] = bj.y; r[3] = bj.z; r[4] = bj.w;
        }
    }
}

// ------------------------------------------------------------------
extern "C" void kernel_launch(void* const* d_in, const int* in_sizes, int n_in,
                              void* d_out, int out_size) {
    const float* loc   = (const float*)d_in[0];
    const float* conf  = (const float*)d_in[1];
    const float* prior = (const float*)d_in[2];
    float* out = (float*)d_out;

    int total = BNUM * PNUM;
    prep_kernel<<<(total + 255) / 256, 256>>>(loc, conf, prior);
    topk_nms_kernel<<<NPAIR, NT>>>(out);
}

// round 7
// speedup vs baseline: 1.3309x; 1.0255x over previous
#include <cuda_runtime.h>
#include <stdint.h>

#define BNUM 32
#define PNUM 8732
#define CFG  20
#define NPAIR (BNUM*CFG)
#define KPRE 256
#define TOPK 200
#define CAP  2048
#define QCAP 1024
#define NT   256
#define TSAMP 128

typedef unsigned long long u64;

// ------------------------------------------------------------------
__device__ uint32_t g_keys[(size_t)NPAIR * PNUM];   // mono(prob) per [b][c][p]
__device__ float4   g_boxes[(size_t)BNUM * PNUM];   // decoded corner boxes

__device__ __forceinline__ uint32_t mono(float f) {
    uint32_t u = __float_as_uint(f);
    return (u & 0x80000000u) ? ~u : (u | 0x80000000u);
}
__device__ __forceinline__ float unmono(uint32_t k) {
    uint32_t u = (k & 0x80000000u) ? (k ^ 0x80000000u) : ~k;
    return __uint_as_float(u);
}

// ------------------------------------------------------------------
// kernel 1: softmax (exact jax.nn.softmax order) + decode
// ------------------------------------------------------------------
__global__ void prep_kernel(const float* __restrict__ loc,
                            const float* __restrict__ conf,
                            const float* __restrict__ prior) {
    int g = blockIdx.x * blockDim.x + threadIdx.x;
    if (g >= BNUM * PNUM) return;
    int b = g / PNUM, p = g % PNUM;

    const float* cp = conf + (size_t)g * 21;
    float x[21];
#pragma unroll
    for (int c = 0; c < 21; c++) x[c] = cp[c];
    float m = x[0];
#pragma unroll
    for (int c = 1; c < 21; c++) m = fmaxf(m, x[c]);
    float e[21];
    float s = 0.f;
#pragma unroll
    for (int c = 0; c < 21; c++) { e[c] = expf(x[c] - m); s += e[c]; }
#pragma unroll
    for (int c = 1; c < 21; c++)
        g_keys[((size_t)b * CFG + (c - 1)) * PNUM + p] = mono(e[c] / s);

    float4 l  = ((const float4*)loc)[g];
    float4 pr = ((const float4*)prior)[p];
    float cx = pr.x + (l.x * 0.1f) * pr.z;
    float cy = pr.y + (l.y * 0.1f) * pr.w;
    float w  = pr.z * expf(l.z * 0.2f);
    float h  = pr.w * expf(l.w * 0.2f);
    float x1 = cx - w * 0.5f;
    float y1 = cy - h * 0.5f;
    g_boxes[g] = make_float4(x1, y1, x1 + w, y1 + h);
}

// ------------------------------------------------------------------
// warp 0 helpers (called by all 32 lanes of warp 0)
// pick highest bin bb with (#keys in bins > bb)+n0 < target <= (#keys >= bb)+n0
// s_sel[0]=bb, s_sel[1]=count strictly above bb.
// ------------------------------------------------------------------
__device__ __forceinline__ void warp_select(const uint32_t* s_hist,
                                            const uint32_t* s_csum,
                                            uint32_t target, uint32_t n0,
                                            volatile uint32_t* s_sel) {
    const int l = threadIdx.x;
    uint32_t v[8]; uint32_t tot = 0;
#pragma unroll
    for (int m = 0; m < 8; m++) { v[m] = s_csum[l * 8 + m]; tot += v[m]; }
    uint32_t incl = tot;
#pragma unroll
    for (int o = 1; o < 32; o <<= 1) {
        uint32_t t = __shfl_down_sync(0xFFFFFFFFu, incl, o);
        if (l + o < 32) incl += t;
    }
    uint32_t above = incl - tot;
    if ((above + n0 < target) && (incl + n0 >= target)) {
        uint32_t acc = above + n0;
        int mm = 0;
        for (int m = 7; m >= 0; m--) {
            if (acc + v[m] >= target) { mm = m; break; }
            acc += v[m];
        }
        int chunk = l * 8 + mm;
        int bb = chunk * 8;
        for (int bi = chunk * 8 + 7; bi >= chunk * 8; bi--) {
            uint32_t h = s_hist[bi];
            if (acc + h >= target) { bb = bi; break; }
            acc += h;
        }
        s_sel[0] = (uint32_t)bb; s_sel[1] = acc;
    }
}

// 256-bin variant: reads histogram directly (8 bins per lane)
__device__ __forceinline__ void warp_select256(const uint32_t* s_hist,
                                               uint32_t target, uint32_t n0,
                                               volatile uint32_t* s_sel) {
    const int l = threadIdx.x;
    uint32_t v[8]; uint32_t tot = 0;
#pragma unroll
    for (int m = 0; m < 8; m++) { v[m] = s_hist[l * 8 + m]; tot += v[m]; }
    uint32_t incl = tot;
#pragma unroll
    for (int o = 1; o < 32; o <<= 1) {
        uint32_t t = __shfl_down_sync(0xFFFFFFFFu, incl, o);
        if (l + o < 32) incl += t;
    }
    uint32_t above = incl - tot;
    if ((above + n0 < target) && (incl + n0 >= target)) {
        uint32_t acc = above + n0;
        int bb = l * 8;
        for (int m = 7; m >= 0; m--) {
            if (acc + v[m] >= target) { bb = l * 8 + m; break; }
            acc += v[m];
        }
        s_sel[0] = (uint32_t)bb; s_sel[1] = acc;
    }
}

// ------------------------------------------------------------------
// kernel 2: per (b,c) pair
// ------------------------------------------------------------------
__global__ __launch_bounds__(NT) void topk_nms_kernel(float* __restrict__ out) {
    __shared__ u64                s_h64[1024];     // hist(2048 u32) / compacted / supp matrix
    __shared__ uint32_t           s_csum[256];
    __shared__ u64                s_cand[CAP];
    __shared__ u64                s_key[KPRE];
    __shared__ float4             s_box[KPRE];
    __shared__ float              s_area[KPRE];
    __shared__ uint32_t           s_keep[8];
    __shared__ uint32_t           s_wpre[8];
    __shared__ uint32_t           s_rowmask[8];
    __shared__ uint32_t           s_sel[2];
    __shared__ uint32_t           s_cnt;
    uint32_t* s_hist = (uint32_t*)s_h64;

    const int pair = blockIdx.x;
    const int b    = pair / CFG;
    const int tid  = threadIdx.x;
    const int wid  = tid >> 5, lane = tid & 31;
    const uint32_t* __restrict__ keys = g_keys + (size_t)pair * PNUM;
    const uint4* __restrict__ keys4 = (const uint4*)keys;
    const int N4 = PNUM / 4;  // 2183

    // ================= sample histogram (25% stride sample, 2184 keys) =================
    for (int i = tid; i < 2048; i += NT) s_hist[i] = 0;
    __syncthreads();
    for (int i = tid; i < 546; i += NT) {
        uint4 k = keys4[i * 4];
        atomicAdd(&s_hist[k.x >> 21], 1u);
        atomicAdd(&s_hist[k.y >> 21], 1u);
        atomicAdd(&s_hist[k.z >> 21], 1u);
        atomicAdd(&s_hist[k.w >> 21], 1u);
    }
    __syncthreads();
    {
        uint32_t cs = 0;
#pragma unroll
        for (int i = 0; i < 8; i++) cs += s_hist[tid * 8 + i];
        s_csum[tid] = cs;
    }
    __syncthreads();
    if (wid == 0) warp_select(s_hist, s_csum, TSAMP, 0, s_sel);
    __syncthreads();
    uint32_t bb0 = s_sel[0];

    // ================= gather: key>>21 >= bb0 =================
    if (tid == 0) s_cnt = 0;
    __syncthreads();
#define TRYPUSH(kk, pp, TH) \
    if (((kk) >> 21) >= (TH)) { \
        uint32_t pos = atomicAdd(&s_cnt, 1u); \
        if (pos < CAP) s_cand[pos] = ((u64)(kk) << 32) | (uint32_t)(~(uint32_t)(pp)); }
    for (int p = tid; p < N4; p += NT) {
        uint4 k = keys4[p];
        int p0 = 4 * p;
        TRYPUSH(k.x, p0,     bb0);
        TRYPUSH(k.y, p0 + 1, bb0);
        TRYPUSH(k.z, p0 + 2, bb0);
        TRYPUSH(k.w, p0 + 3, bb0);
    }
    __syncthreads();
    uint32_t M = s_cnt;

    // ================= fallback: exact global select (rare) =================
    if (M < KPRE || M > CAP) {
        for (int i = tid; i < 2048; i += NT) s_hist[i] = 0;
        __syncthreads();
        for (int p = tid; p < N4; p += NT) {
            uint4 k = keys4[p];
            atomicAdd(&s_hist[k.x >> 21], 1u);
            atomicAdd(&s_hist[k.y >> 21], 1u);
            atomicAdd(&s_hist[k.z >> 21], 1u);
            atomicAdd(&s_hist[k.w >> 21], 1u);
        }
        __syncthreads();
        {
            uint32_t cs = 0;
#pragma unroll
            for (int i = 0; i < 8; i++) cs += s_hist[tid * 8 + i];
            s_csum[tid] = cs;
        }
        __syncthreads();
        if (wid == 0) warp_select(s_hist, s_csum, KPRE, 0, s_sel);
        __syncthreads();
        uint32_t bbe = s_sel[0], n_above = s_sel[1];
        if (tid == 0) s_cnt = 0;
        __syncthreads();
        for (int p = tid; p < N4; p += NT) {
            uint4 k = keys4[p];
            int p0 = 4 * p;
            TRYPUSH(k.x, p0,     bbe);
            TRYPUSH(k.y, p0 + 1, bbe);
            TRYPUSH(k.z, p0 + 2, bbe);
            TRYPUSH(k.w, p0 + 3, bbe);
        }
        __syncthreads();
        M = s_cnt;
        if (M > CAP) {   // boundary bin too fat: refine globally to 21 bits
            for (int i = tid; i < 2048; i += NT) s_hist[i] = 0;
            __syncthreads();
            for (int p = tid; p < PNUM; p += NT) {
                uint32_t k = keys[p];
                if ((k >> 21) == bbe) atomicAdd(&s_hist[(k >> 10) & 0x7FFu], 1u);
            }
            __syncthreads();
            {
                uint32_t cs = 0;
#pragma unroll
                for (int i = 0; i < 8; i++) cs += s_hist[tid * 8 + i];
                s_csum[tid] = cs;
            }
            __syncthreads();
            if (wid == 0) warp_select(s_hist, s_csum, KPRE, n_above, s_sel);
            __syncthreads();
            uint32_t pref21 = (bbe << 11) | s_sel[0];
            if (tid == 0) s_cnt = 0;
            __syncthreads();
            for (int p = tid; p < PNUM; p += NT) {
                uint32_t k = keys[p];
                if ((k >> 10) >= pref21) {
                    uint32_t pos = atomicAdd(&s_cnt, 1u);
                    if (pos < CAP) s_cand[pos] = ((u64)k << 32) | (uint32_t)(~(uint32_t)p);
                }
            }
            __syncthreads();
            M = s_cnt;
            if (M > CAP) M = CAP;
        }
    }
#undef TRYPUSH

    // ============ in-shared refine, 4 levels x 8-bit digits -> exact F ============
    uint32_t pref = 0, n0 = 0;
#pragma unroll
    for (int lev = 0; lev < 4; lev++) {
        const int sh = 24 - lev * 8;
        if (tid < 256) s_hist[tid] = 0;
        __syncthreads();
        for (uint32_t i = tid; i < M; i += NT) {
            uint32_t k = (uint32_t)(s_cand[i] >> 32);
            bool match = (lev == 0) || ((k >> (sh + 8)) == pref);
            if (match) atomicAdd(&s_hist[(k >> sh) & 255u], 1u);
        }
        __syncthreads();
        if (wid == 0) warp_select256(s_hist, KPRE, n0, s_sel);
        __syncthreads();
        pref = (pref << 8) | s_sel[0];
        n0 = s_sel[1];
        __syncthreads();
    }
    uint32_t F = pref;

    // ================= compact qualifying (key >= F) =================
    if (tid == 0) s_cnt = 0;
    __syncthreads();
    for (uint32_t i = tid; i < M; i += NT) {
        u64 c = s_cand[i];
        if ((uint32_t)(c >> 32) >= F) {
            uint32_t pos = atomicAdd(&s_cnt, 1u);
            if (pos < QCAP) s_h64[pos] = c;
        }
    }
    __syncthreads();
    uint32_t M2 = s_cnt; if (M2 > QCAP) M2 = QCAP;

    // ================= sort: bitonic-256 (generic) or rank-sort (ties) =================
    if (M2 == KPRE) {
        u64 mine = s_h64[tid];
        __syncthreads();
#pragma unroll
        for (uint32_t k = 2; k <= 256; k <<= 1) {
            for (uint32_t j = k >> 1; j >= 1; j >>= 1) {
                u64 other;
                if (j >= 32) {
                    s_key[tid] = mine;
                    __syncthreads();
                    other = s_key[tid ^ j];
                    __syncthreads();
                } else {
                    other = __shfl_xor_sync(0xFFFFFFFFu, mine, j);
                }
                bool lower   = (tid & j) == 0;
                bool dirDesc = (tid & k) == 0;
                bool takeMax = (lower == dirDesc);
                u64 mx = mine > other ? mine : other;
                u64 mn = mine > other ? other : mine;
                mine = takeMax ? mx : mn;
            }
        }
        s_key[tid] = mine;
    } else {
        for (uint32_t i = tid; i < M2; i += NT) {
            u64 mine = s_h64[i];
            uint32_t rank = 0;
            for (uint32_t j = 0; j < M2; j++) rank += (s_h64[j] > mine);
            if (rank < KPRE) s_key[rank] = mine;
        }
    }
    __syncthreads();

    // ================= extract top-256 =================
    u64 key = s_key[tid];
    uint32_t idx = ~(uint32_t)key;
    float scv = unmono((uint32_t)(key >> 32));
    float4 bj = g_boxes[(size_t)b * PNUM + idx];
    float aj = fmaxf(bj.z - bj.x, 0.f) * fmaxf(bj.w - bj.y, 0.f);
    s_box[tid]  = bj;
    s_area[tid] = aj;
    {
        bool valid = scv > 0.01f;
        uint32_t bal = __ballot_sync(0xFFFFFFFFu, valid);
        if (lane == 0) s_keep[wid] = bal;
    }
    if (tid < 8) s_rowmask[tid] = 0;
    // hoist output zeroing: global stores drain while bitmatrix computes
    float* op = out + (size_t)pair * (TOPK * 5);
    for (int i = tid; i < TOPK * 5; i += NT) op[i] = 0.f;
    uint32_t* s_supp = (uint32_t*)s_h64;
    __syncthreads();

    // ===== suppression bitmatrix: balanced schedule + rowmask for sparse scan =====
    for (int g = 0; g < 8; g++) {
        const int   colg = g * 32 + lane;
        const float4 bg  = s_box[colg];
        const float  ag  = s_area[colg];
        const int    imax = g * 32 + 32;
        for (int i = wid; i < imax; i += 8) {
            float4 bi = s_box[i];
            float wx = fmaxf(fminf(bi.z, bg.z) - fmaxf(bi.x, bg.x), 0.f);
            float wy = fmaxf(fminf(bi.w, bg.w) - fmaxf(bi.y, bg.y), 0.f);
            float inter = __fmul_rn(wx, wy);
            float uni = __fadd_rn(__fadd_rn(s_area[i], ag), -inter);
            float ut = fmaxf(uni, 1e-9f);
            bool gt  = colg > i;
            bool sup = gt && (inter > __fmul_rn(0.45004f, ut));
            if (gt && !sup && inter >= __fmul_rn(0.44996f, ut))
                sup = (inter / ut) > 0.45f;        // exact IEEE path, ~never taken
            uint32_t bal = __ballot_sync(0xFFFFFFFFu, sup);
            if (lane == 0) {
                s_supp[i * 8 + g] = bal;
                if (bal) atomicOr(&s_rowmask[i >> 5], 1u << (i & 31));
            }
        }
    }
    __syncthreads();

    // ====== sparse greedy scan on warp 0 (only rows that suppress someone) ======
    if (wid == 0) {
        uint32_t kw = (lane < 8) ? s_keep[lane] : 0u;
        for (int w8 = 0; w8 < 8; w8++) {
            uint32_t rm = s_rowmask[w8];
            while (rm) {
                int bit = __ffs(rm) - 1; rm &= rm - 1;
                int i = w8 * 32 + bit;
                // word containing bit i (current keep state)
                uint32_t w = __shfl_sync(0xFFFFFFFFu, kw, w8);
                // row i's suppression word for this lane (triangle: valid iff lane >= w8)
                uint32_t cur = (lane < 8 && lane >= w8) ? s_supp[i * 8 + lane] : 0u;
                if ((w >> bit) & 1u)
                    kw &= ~cur;
            }
        }
        if (lane < 8) s_keep[lane] = kw;
    }
    __syncthreads();

    // ================= compaction + output =================
    if (tid == 0) {
        uint32_t a = 0;
#pragma unroll
        for (int w2 = 0; w2 < 8; w2++) { s_wpre[w2] = a; a += __popc(s_keep[w2]); }
    }
    __syncthreads();

    uint32_t kwm = s_keep[wid];
    if ((kwm >> lane) & 1u) {
        uint32_t rank = s_wpre[wid] + __popc(kwm & ((1u << lane) - 1u));
        if (rank < TOPK) {
            float* r = op + (size_t)rank * 5;
            r[0] = scv;
            r[1] = bj.x; r[2] = bj.y; r[3] = bj.z; r[4] = bj.w;
        }
    }
}

// ------------------------------------------------------------------
extern "C" void kernel_launch(void* const* d_in, const int* in_sizes, int n_in,
                              void* d_out, int out_size) {
    const float* loc   = (const float*)d_in[0];
    const float* conf  = (const float*)d_in[1];
    const float* prior = (const float*)d_in[2];
    float* out = (float*)d_out;

    int total = BNUM * PNUM;
    prep_kernel<<<(total + 255) / 256, 256>>>(loc, conf, prior);
    topk_nms_kernel<<<NPAIR, NT>>>(out);
}

// round 9
// speedup vs baseline: 1.3341x; 1.0024x over previous
#include <cuda_runtime.h>
#include <stdint.h>

#define BNUM 32
#define PNUM 8732
#define CFG  20
#define NPAIR (BNUM*CFG)
#define KPRE 256
#define TOPK 200
#define CAP  2048
#define QCAP 1024
#define NT   256
#define TSAMP 128

typedef unsigned long long u64;

// ------------------------------------------------------------------
__device__ uint32_t g_keys[(size_t)NPAIR * PNUM];   // mono(prob) per [b][c][p]

__device__ __forceinline__ uint32_t mono(float f) {
    uint32_t u = __float_as_uint(f);
    return (u & 0x80000000u) ? ~u : (u | 0x80000000u);
}
__device__ __forceinline__ float unmono(uint32_t k) {
    uint32_t u = (k & 0x80000000u) ? (k ^ 0x80000000u) : ~k;
    return __uint_as_float(u);
}

// ------------------------------------------------------------------
// kernel 1: softmax only (exact jax.nn.softmax order) -> mono keys
// ------------------------------------------------------------------
__global__ void prep_kernel(const float* __restrict__ conf) {
    int g = blockIdx.x * blockDim.x + threadIdx.x;
    if (g >= BNUM * PNUM) return;
    int b = g / PNUM, p = g % PNUM;

    const float* cp = conf + (size_t)g * 21;
    float x[21];
#pragma unroll
    for (int c = 0; c < 21; c++) x[c] = cp[c];
    float m = x[0];
#pragma unroll
    for (int c = 1; c < 21; c++) m = fmaxf(m, x[c]);
    float e[21];
    float s = 0.f;
#pragma unroll
    for (int c = 0; c < 21; c++) { e[c] = expf(x[c] - m); s += e[c]; }
#pragma unroll
    for (int c = 1; c < 21; c++)
        g_keys[((size_t)b * CFG + (c - 1)) * PNUM + p] = mono(e[c] / s);
}

// ------------------------------------------------------------------
// warp 0 helpers (called by all 32 lanes of warp 0)
// ------------------------------------------------------------------
__device__ __forceinline__ void warp_select(const uint32_t* s_hist,
                                            const uint32_t* s_csum,
                                            uint32_t target, uint32_t n0,
                                            volatile uint32_t* s_sel) {
    const int l = threadIdx.x;
    uint32_t v[8]; uint32_t tot = 0;
#pragma unroll
    for (int m = 0; m < 8; m++) { v[m] = s_csum[l * 8 + m]; tot += v[m]; }
    uint32_t incl = tot;
#pragma unroll
    for (int o = 1; o < 32; o <<= 1) {
        uint32_t t = __shfl_down_sync(0xFFFFFFFFu, incl, o);
        if (l + o < 32) incl += t;
    }
    uint32_t above = incl - tot;
    if ((above + n0 < target) && (incl + n0 >= target)) {
        uint32_t acc = above + n0;
        int mm = 0;
        for (int m = 7; m >= 0; m--) {
            if (acc + v[m] >= target) { mm = m; break; }
            acc += v[m];
        }
        int chunk = l * 8 + mm;
        int bb = chunk * 8;
        for (int bi = chunk * 8 + 7; bi >= chunk * 8; bi--) {
            uint32_t h = s_hist[bi];
            if (acc + h >= target) { bb = bi; break; }
            acc += h;
        }
        s_sel[0] = (uint32_t)bb; s_sel[1] = acc;
    }
}

__device__ __forceinline__ void warp_select256(const uint32_t* s_hist,
                                               uint32_t target, uint32_t n0,
                                               volatile uint32_t* s_sel) {
    const int l = threadIdx.x;
    uint32_t v[8]; uint32_t tot = 0;
#pragma unroll
    for (int m = 0; m < 8; m++) { v[m] = s_hist[l * 8 + m]; tot += v[m]; }
    uint32_t incl = tot;
#pragma unroll
    for (int o = 1; o < 32; o <<= 1) {
        uint32_t t = __shfl_down_sync(0xFFFFFFFFu, incl, o);
        if (l + o < 32) incl += t;
    }
    uint32_t above = incl - tot;
    if ((above + n0 < target) && (incl + n0 >= target)) {
        uint32_t acc = above + n0;
        int bb = l * 8;
        for (int m = 7; m >= 0; m--) {
            if (acc + v[m] >= target) { bb = l * 8 + m; break; }
            acc += v[m];
        }
        s_sel[0] = (uint32_t)bb; s_sel[1] = acc;
    }
}

// warp-aggregated candidate push (1 atomic per warp-site).
// MUST be reached by all 32 lanes of the warp (uniform control flow).
__device__ __forceinline__ void push_agg(bool q, uint32_t kk, uint32_t pp,
                                         uint32_t* cnt, u64* buf, uint32_t cap) {
    const int lane = threadIdx.x & 31;
    uint32_t bal = __ballot_sync(0xFFFFFFFFu, q);
    if (bal) {
        int ldr = __ffs(bal) - 1;
        uint32_t base = 0;
        if (lane == ldr) base = atomicAdd(cnt, (uint32_t)__popc(bal));
        base = __shfl_sync(0xFFFFFFFFu, base, ldr);
        if (q) {
            uint32_t pos = base + __popc(bal & ((1u << lane) - 1u));
            if (pos < cap) buf[pos] = ((u64)kk << 32) | (uint32_t)(~pp);
        }
    }
}

// ------------------------------------------------------------------
// kernel 2: per (b,c) pair
// ------------------------------------------------------------------
__global__ __launch_bounds__(NT) void topk_nms_kernel(float* __restrict__ out,
                                                      const float* __restrict__ loc,
                                                      const float* __restrict__ prior) {
    __shared__ u64                s_h64[1024];     // hist(2048 u32) / compacted / supp matrix
    __shared__ uint32_t           s_csum[256];
    __shared__ u64                s_cand[CAP];
    __shared__ u64                s_key[KPRE];
    __shared__ float4             s_box[KPRE];
    __shared__ float              s_area[KPRE];
    __shared__ uint32_t           s_keep[8];
    __shared__ uint32_t           s_wpre[8];
    __shared__ uint32_t           s_rowmask[8];
    __shared__ uint32_t           s_sel[2];
    __shared__ uint32_t           s_cnt;
    uint32_t* s_hist = (uint32_t*)s_h64;

    const int pair = blockIdx.x;
    const int b    = pair / CFG;
    const int tid  = threadIdx.x;
    const int wid  = tid >> 5, lane = tid & 31;
    const uint32_t* __restrict__ keys = g_keys + (size_t)pair * PNUM;
    const uint4* __restrict__ keys4 = (const uint4*)keys;
    const int N4 = PNUM / 4;               // 2183
    const int N4CEIL = ((N4 + NT - 1) / NT) * NT;   // uniform trip count

    // ================= sample histogram (25% stride sample, 2184 keys) =================
    for (int i = tid; i < 2048; i += NT) s_hist[i] = 0;
    __syncthreads();
    for (int i = tid; i < 546; i += NT) {
        uint4 k = keys4[i * 4];
        atomicAdd(&s_hist[k.x >> 21], 1u);
        atomicAdd(&s_hist[k.y >> 21], 1u);
        atomicAdd(&s_hist[k.z >> 21], 1u);
        atomicAdd(&s_hist[k.w >> 21], 1u);
    }
    __syncthreads();
    {
        uint32_t cs = 0;
#pragma unroll
        for (int i = 0; i < 8; i++) cs += s_hist[tid * 8 + i];
        s_csum[tid] = cs;
    }
    __syncthreads();
    if (wid == 0) warp_select(s_hist, s_csum, TSAMP, 0, s_sel);
    __syncthreads();
    uint32_t bb0 = s_sel[0];

    // ========= gather: key>>21 >= bb0 (warp-aggregated, uniform trip count) =========
    if (tid == 0) s_cnt = 0;
    __syncthreads();
    for (int pb = 0; pb < N4CEIL; pb += NT) {
        int p = pb + tid;
        bool in = p < N4;
        uint4 k = in ? keys4[p] : make_uint4(0, 0, 0, 0);
        uint32_t p0 = 4 * (uint32_t)p;
        push_agg(in && ((k.x >> 21) >= bb0), k.x, p0,     &s_cnt, s_cand, CAP);
        push_agg(in && ((k.y >> 21) >= bb0), k.y, p0 + 1, &s_cnt, s_cand, CAP);
        push_agg(in && ((k.z >> 21) >= bb0), k.z, p0 + 2, &s_cnt, s_cand, CAP);
        push_agg(in && ((k.w >> 21) >= bb0), k.w, p0 + 3, &s_cnt, s_cand, CAP);
    }
    __syncthreads();
    uint32_t M = s_cnt;

    // ================= fallback: exact global select (rare) =================
    if (M < KPRE || M > CAP) {
        for (int i = tid; i < 2048; i += NT) s_hist[i] = 0;
        __syncthreads();
        for (int p = tid; p < N4; p += NT) {
            uint4 k = keys4[p];
            atomicAdd(&s_hist[k.x >> 21], 1u);
            atomicAdd(&s_hist[k.y >> 21], 1u);
            atomicAdd(&s_hist[k.z >> 21], 1u);
            atomicAdd(&s_hist[k.w >> 21], 1u);
        }
        __syncthreads();
        {
            uint32_t cs = 0;
#pragma unroll
            for (int i = 0; i < 8; i++) cs += s_hist[tid * 8 + i];
            s_csum[tid] = cs;
        }
        __syncthreads();
        if (wid == 0) warp_select(s_hist, s_csum, KPRE, 0, s_sel);
        __syncthreads();
        uint32_t bbe = s_sel[0], n_above = s_sel[1];
        if (tid == 0) s_cnt = 0;
        __syncthreads();
        for (int pb = 0; pb < N4CEIL; pb += NT) {
            int p = pb + tid;
            bool in = p < N4;
            uint4 k = in ? keys4[p] : make_uint4(0, 0, 0, 0);
            uint32_t p0 = 4 * (uint32_t)p;
            push_agg(in && ((k.x >> 21) >= bbe), k.x, p0,     &s_cnt, s_cand, CAP);
            push_agg(in && ((k.y >> 21) >= bbe), k.y, p0 + 1, &s_cnt, s_cand, CAP);
            push_agg(in && ((k.z >> 21) >= bbe), k.z, p0 + 2, &s_cnt, s_cand, CAP);
            push_agg(in && ((k.w >> 21) >= bbe), k.w, p0 + 3, &s_cnt, s_cand, CAP);
        }
        __syncthreads();
        M = s_cnt;
        if (M > CAP) {   // boundary bin too fat: refine globally to 21 bits
            for (int i = tid; i < 2048; i += NT) s_hist[i] = 0;
            __syncthreads();
            for (int p = tid; p < PNUM; p += NT) {
                uint32_t k = keys[p];
                if ((k >> 21) == bbe) atomicAdd(&s_hist[(k >> 10) & 0x7FFu], 1u);
            }
            __syncthreads();
            {
                uint32_t cs = 0;
#pragma unroll
                for (int i = 0; i < 8; i++) cs += s_hist[tid * 8 + i];
                s_csum[tid] = cs;
            }
            __syncthreads();
            if (wid == 0) warp_select(s_hist, s_csum, KPRE, n_above, s_sel);
            __syncthreads();
            uint32_t pref21 = (bbe << 11) | s_sel[0];
            if (tid == 0) s_cnt = 0;
            __syncthreads();
            const int PCEIL = ((PNUM + NT - 1) / NT) * NT;
            for (int pb = 0; pb < PCEIL; pb += NT) {
                int p = pb + tid;
                bool in = p < PNUM;
                uint32_t k = in ? keys[p] : 0u;
                push_agg(in && ((k >> 10) >= pref21), k, (uint32_t)p, &s_cnt, s_cand, CAP);
            }
            __syncthreads();
            M = s_cnt;
            if (M > CAP) M = CAP;
        }
    }

    // ============ in-shared refine, 4 levels x 8-bit digits -> exact F ============
    uint32_t pref = 0, n0 = 0;
#pragma unroll
    for (int lev = 0; lev < 4; lev++) {
        const int sh = 24 - lev * 8;
        if (tid < 256) s_hist[tid] = 0;
        __syncthreads();
        for (uint32_t i = tid; i < M; i += NT) {
            uint32_t k = (uint32_t)(s_cand[i] >> 32);
            bool match = (lev == 0) || ((k >> (sh + 8)) == pref);
            if (match) atomicAdd(&s_hist[(k >> sh) & 255u], 1u);
        }
        __syncthreads();
        if (wid == 0) warp_select256(s_hist, KPRE, n0, s_sel);
        __syncthreads();
        pref = (pref << 8) | s_sel[0];
        n0 = s_sel[1];
    }
    uint32_t F = pref;

    // ========== compact qualifying (key >= F), uniform trip count ==========
    __syncthreads();   // retire last hist reads before reusing s_h64
    if (tid == 0) s_cnt = 0;
    __syncthreads();
    {
        uint32_t MCEIL = ((M + NT - 1) / NT) * NT;
        for (uint32_t ib = 0; ib < MCEIL; ib += NT) {
            uint32_t i = ib + tid;
            bool in = i < M;
            u64 c = in ? s_cand[i] : 0ULL;
            uint32_t kk = (uint32_t)(c >> 32);
            push_agg(in && (kk >= F), kk, ~(uint32_t)c, &s_cnt, s_h64, QCAP);
        }
    }
    __syncthreads();
    uint32_t M2 = s_cnt; if (M2 > QCAP) M2 = QCAP;

    // ================= sort: bitonic-256 (generic) or rank-sort (ties) =================
    if (M2 == KPRE) {
        u64 mine = s_h64[tid];
        __syncthreads();
#pragma unroll
        for (uint32_t k = 2; k <= 256; k <<= 1) {
            for (uint32_t j = k >> 1; j >= 1; j >>= 1) {
                u64 other;
                if (j >= 32) {
                    s_key[tid] = mine;
                    __syncthreads();
                    other = s_key[tid ^ j];
                    __syncthreads();
                } else {
                    other = __shfl_xor_sync(0xFFFFFFFFu, mine, j);
                }
                bool lower   = (tid & j) == 0;
                bool dirDesc = (tid & k) == 0;
                bool takeMax = (lower == dirDesc);
                u64 mx = mine > other ? mine : other;
                u64 mn = mine > other ? other : mine;
                mine = takeMax ? mx : mn;
            }
        }
        s_key[tid] = mine;
    } else {
        for (uint32_t i = tid; i < M2; i += NT) {
            u64 mine = s_h64[i];
            uint32_t rank = 0;
            for (uint32_t j = 0; j < M2; j++) rank += (s_h64[j] > mine);
            if (rank < KPRE) s_key[rank] = mine;
        }
    }
    __syncthreads();

    // ======== extract top-256: decode box on demand (exact prep arithmetic) ========
    u64 key = s_key[tid];
    uint32_t idx = ~(uint32_t)key;
    float scv = unmono((uint32_t)(key >> 32));
    float4 bj;
    {
        float4 l  = __ldg((const float4*)loc + (size_t)b * PNUM + idx);
        float4 pr = __ldg((const float4*)prior + idx);
        float cx = pr.x + (l.x * 0.1f) * pr.z;
        float cy = pr.y + (l.y * 0.1f) * pr.w;
        float w  = pr.z * expf(l.z * 0.2f);
        float h  = pr.w * expf(l.w * 0.2f);
        float x1 = cx - w * 0.5f;
        float y1 = cy - h * 0.5f;
        bj = make_float4(x1, y1, x1 + w, y1 + h);
    }
    float aj = fmaxf(bj.z - bj.x, 0.f) * fmaxf(bj.w - bj.y, 0.f);
    s_box[tid]  = bj;
    s_area[tid] = aj;
    {
        bool valid = scv > 0.01f;
        uint32_t bal = __ballot_sync(0xFFFFFFFFu, valid);
        if (lane == 0) s_keep[wid] = bal;
    }
    if (tid < 8) s_rowmask[tid] = 0;
    float* op = out + (size_t)pair * (TOPK * 5);
    for (int i = tid; i < TOPK * 5; i += NT) op[i] = 0.f;
    uint32_t* s_supp = (uint32_t*)s_h64;
    __syncthreads();

    // ===== suppression bitmatrix: balanced schedule, 4-wide unrolled rows =====
#pragma unroll 1
    for (int g = 0; g < 8; g++) {
        const int    colg = g * 32 + lane;
        const float4 bg   = s_box[colg];
        const float  ag   = s_area[colg];
        const int    nT   = g + 1;          // row count = 4*(g+1), groups of 4
#pragma unroll 1
        for (int t = 0; t < nT; t++) {
#pragma unroll
            for (int u = 0; u < 4; u++) {
                const int i = wid + t * 32 + u * 8;
                float4 bi = s_box[i];
                float wx = fmaxf(fminf(bi.z, bg.z) - fmaxf(bi.x, bg.x), 0.f);
                float wy = fmaxf(fminf(bi.w, bg.w) - fmaxf(bi.y, bg.y), 0.f);
                float inter = __fmul_rn(wx, wy);
                float uni = __fadd_rn(__fadd_rn(s_area[i], ag), -inter);
                float ut = fmaxf(uni, 1e-9f);
                bool gt  = colg > i;
                bool sup = gt && (inter > __fmul_rn(0.45004f, ut));
                if (gt && !sup && inter >= __fmul_rn(0.44996f, ut))
                    sup = (inter / ut) > 0.45f;        // exact IEEE path, ~never taken
                uint32_t bal = __ballot_sync(0xFFFFFFFFu, sup);
                if (lane == 0) {
                    s_supp[i * 8 + g] = bal;
                    if (bal) atomicOr(&s_rowmask[i >> 5], 1u << (i & 31));
                }
            }
        }
    }
    __syncthreads();

    // ====== sparse greedy scan on warp 0 (only rows that suppress someone) ======
    if (wid == 0) {
        uint32_t kw = (lane < 8) ? s_keep[lane] : 0u;
        for (int w8 = 0; w8 < 8; w8++) {
            uint32_t rm = s_rowmask[w8];
            while (rm) {
                int bit = __ffs(rm) - 1; rm &= rm - 1;
                int i = w8 * 32 + bit;
                uint32_t w = __shfl_sync(0xFFFFFFFFu, kw, w8);
                uint32_t cur = (lane < 8 && lane >= w8) ? s_supp[i * 8 + lane] : 0u;
                if ((w >> bit) & 1u)
                    kw &= ~cur;
            }
        }
        if (lane < 8) s_keep[lane] = kw;
    }
    __syncthreads();

    // ================= compaction + output =================
    if (tid == 0) {
        uint32_t a = 0;
#pragma unroll
        for (int w2 = 0; w2 < 8; w2++) { s_wpre[w2] = a; a += __popc(s_keep[w2]); }
    }
    __syncthreads();

    uint32_t kwm = s_keep[wid];
    if ((kwm >> lane) & 1u) {
        uint32_t rank = s_wpre[wid] + __popc(kwm & ((1u << lane) - 1u));
        if (rank < TOPK) {
            float* r = op + (size_t)rank * 5;
            r[0] = scv;
            r[1] = bj.x; r[2] = bj.y; r[3] = bj.z; r[4] = bj.w;
        }
    }
}

// ------------------------------------------------------------------
extern "C" void kernel_launch(void* const* d_in, const int* in_sizes, int n_in,
                              void* d_out, int out_size) {
    const float* loc   = (const float*)d_in[0];
    const float* conf  = (const float*)d_in[1];
    const float* prior = (const float*)d_in[2];
    float* out = (float*)d_out;

    int total = BNUM * PNUM;
    prep_kernel<<<(total + 255) / 256, 256>>>(conf);
    topk_nms_kernel<<<NPAIR, NT>>>(out, loc, prior);
}

// round 10
// speedup vs baseline: 1.4807x; 1.1099x over previous
#include <cuda_runtime.h>
#include <stdint.h>

#define BNUM 32
#define PNUM 8732
#define CFG  20
#define NPAIR (BNUM*CFG)
#define KPRE 256
#define TOPK 200
#define CAP  2048
#define QCAP 1024
#define NT   256
#define TSAMP 128

typedef unsigned long long u64;

// ------------------------------------------------------------------
__device__ uint32_t g_keys[(size_t)NPAIR * PNUM];   // mono(prob) per [b][c][p]

__device__ __forceinline__ uint32_t mono(float f) {
    uint32_t u = __float_as_uint(f);
    return (u & 0x80000000u) ? ~u : (u | 0x80000000u);
}
__device__ __forceinline__ float unmono(uint32_t k) {
    uint32_t u = (k & 0x80000000u) ? (k ^ 0x80000000u) : ~k;
    return __uint_as_float(u);
}

// ------------------------------------------------------------------
// kernel 1: softmax only (exact jax.nn.softmax order) -> mono keys
// ------------------------------------------------------------------
__global__ void prep_kernel(const float* __restrict__ conf) {
    int g = blockIdx.x * blockDim.x + threadIdx.x;
    if (g >= BNUM * PNUM) return;
    int b = g / PNUM, p = g % PNUM;

    const float* cp = conf + (size_t)g * 21;
    float x[21];
#pragma unroll
    for (int c = 0; c < 21; c++) x[c] = cp[c];
    float m = x[0];
#pragma unroll
    for (int c = 1; c < 21; c++) m = fmaxf(m, x[c]);
    float e[21];
    float s = 0.f;
#pragma unroll
    for (int c = 0; c < 21; c++) { e[c] = expf(x[c] - m); s += e[c]; }
#pragma unroll
    for (int c = 1; c < 21; c++)
        g_keys[((size_t)b * CFG + (c - 1)) * PNUM + p] = mono(e[c] / s);
}

// ------------------------------------------------------------------
// warp 0 helpers (called by all 32 lanes of warp 0)
// ------------------------------------------------------------------
__device__ __forceinline__ void warp_select(const uint32_t* s_hist,
                                            const uint32_t* s_csum,
                                            uint32_t target, uint32_t n0,
                                            volatile uint32_t* s_sel) {
    const int l = threadIdx.x;
    uint32_t v[8]; uint32_t tot = 0;
#pragma unroll
    for (int m = 0; m < 8; m++) { v[m] = s_csum[l * 8 + m]; tot += v[m]; }
    uint32_t incl = tot;
#pragma unroll
    for (int o = 1; o < 32; o <<= 1) {
        uint32_t t = __shfl_down_sync(0xFFFFFFFFu, incl, o);
        if (l + o < 32) incl += t;
    }
    uint32_t above = incl - tot;
    if ((above + n0 < target) && (incl + n0 >= target)) {
        uint32_t acc = above + n0;
        int mm = 0;
        for (int m = 7; m >= 0; m--) {
            if (acc + v[m] >= target) { mm = m; break; }
            acc += v[m];
        }
        int chunk = l * 8 + mm;
        int bb = chunk * 8;
        for (int bi = chunk * 8 + 7; bi >= chunk * 8; bi--) {
            uint32_t h = s_hist[bi];
            if (acc + h >= target) { bb = bi; break; }
            acc += h;
        }
        s_sel[0] = (uint32_t)bb; s_sel[1] = acc;
    }
}

__device__ __forceinline__ void warp_select256(const uint32_t* s_hist,
                                               uint32_t target, uint32_t n0,
                                               volatile uint32_t* s_sel) {
    const int l = threadIdx.x;
    uint32_t v[8]; uint32_t tot = 0;
#pragma unroll
    for (int m = 0; m < 8; m++) { v[m] = s_hist[l * 8 + m]; tot += v[m]; }
    uint32_t incl = tot;
#pragma unroll
    for (int o = 1; o < 32; o <<= 1) {
        uint32_t t = __shfl_down_sync(0xFFFFFFFFu, incl, o);
        if (l + o < 32) incl += t;
    }
    uint32_t above = incl - tot;
    if ((above + n0 < target) && (incl + n0 >= target)) {
        uint32_t acc = above + n0;
        int bb = l * 8;
        for (int m = 7; m >= 0; m--) {
            if (acc + v[m] >= target) { bb = l * 8 + m; break; }
            acc += v[m];
        }
        s_sel[0] = (uint32_t)bb; s_sel[1] = acc;
    }
}

// ------------------------------------------------------------------
// kernel 2: per (b,c) pair
// ------------------------------------------------------------------
__global__ __launch_bounds__(NT) void topk_nms_kernel(float* __restrict__ out,
                                                      const float* __restrict__ loc,
                                                      const float* __restrict__ prior) {
    __shared__ u64                s_h64[1024];     // hist(2048 u32) / compacted / supp matrix
    __shared__ uint32_t           s_csum[256];
    __shared__ u64                s_cand[CAP];
    __shared__ u64                s_key[KPRE];
    __shared__ float4             s_box[KPRE];
    __shared__ float              s_area[KPRE];
    __shared__ uint32_t           s_keep[8];
    __shared__ uint32_t           s_wpre[8];
    __shared__ uint32_t           s_rowmask[8];
    __shared__ uint32_t           s_sel[2];
    __shared__ uint32_t           s_cnt;
    uint32_t* s_hist = (uint32_t*)s_h64;

    const int pair = blockIdx.x;
    const int b    = pair / CFG;
    const int tid  = threadIdx.x;
    const int wid  = tid >> 5, lane = tid & 31;
    const uint32_t* __restrict__ keys = g_keys + (size_t)pair * PNUM;
    const uint4* __restrict__ keys4 = (const uint4*)keys;
    const int N4 = PNUM / 4;  // 2183 (exact: 8732 = 4*2183)

    // ================= sample histogram (25% stride sample, 2184 keys) =================
    for (int i = tid; i < 2048; i += NT) s_hist[i] = 0;
    __syncthreads();
    for (int i = tid; i < 546; i += NT) {
        uint4 k = keys4[i * 4];
        atomicAdd(&s_hist[k.x >> 21], 1u);
        atomicAdd(&s_hist[k.y >> 21], 1u);
        atomicAdd(&s_hist[k.z >> 21], 1u);
        atomicAdd(&s_hist[k.w >> 21], 1u);
    }
    __syncthreads();
    {
        uint32_t cs = 0;
#pragma unroll
        for (int i = 0; i < 8; i++) cs += s_hist[tid * 8 + i];
        s_csum[tid] = cs;
    }
    __syncthreads();
    if (wid == 0) warp_select(s_hist, s_csum, TSAMP, 0, s_sel);
    __syncthreads();
    const uint32_t T0 = s_sel[0] << 21;      // direct 32-bit threshold

    // ================= gather: key >= T0 (plain per-lane atomics) =================
    if (tid == 0) s_cnt = 0;
    __syncthreads();
#define TRYPUSH(kk, pp, TH) \
    if ((kk) >= (TH)) { \
        uint32_t pos = atomicAdd(&s_cnt, 1u); \
        if (pos < CAP) s_cand[pos] = ((u64)(kk) << 32) | (uint32_t)(~(uint32_t)(pp)); }
    for (int p = tid; p < N4; p += NT) {
        uint4 k = keys4[p];
        int p0 = 4 * p;
        TRYPUSH(k.x, p0,     T0);
        TRYPUSH(k.y, p0 + 1, T0);
        TRYPUSH(k.z, p0 + 2, T0);
        TRYPUSH(k.w, p0 + 3, T0);
    }
    __syncthreads();
    uint32_t M = s_cnt;

    // ================= fallback: exact global select (rare) =================
    if (M < KPRE || M > CAP) {
        for (int i = tid; i < 2048; i += NT) s_hist[i] = 0;
        __syncthreads();
        for (int p = tid; p < N4; p += NT) {
            uint4 k = keys4[p];
            atomicAdd(&s_hist[k.x >> 21], 1u);
            atomicAdd(&s_hist[k.y >> 21], 1u);
            atomicAdd(&s_hist[k.z >> 21], 1u);
            atomicAdd(&s_hist[k.w >> 21], 1u);
        }
        __syncthreads();
        {
            uint32_t cs = 0;
#pragma unroll
            for (int i = 0; i < 8; i++) cs += s_hist[tid * 8 + i];
            s_csum[tid] = cs;
        }
        __syncthreads();
        if (wid == 0) warp_select(s_hist, s_csum, KPRE, 0, s_sel);
        __syncthreads();
        uint32_t bbe = s_sel[0], n_above = s_sel[1];
        uint32_t Te = bbe << 21;
        if (tid == 0) s_cnt = 0;
        __syncthreads();
        for (int p = tid; p < N4; p += NT) {
            uint4 k = keys4[p];
            int p0 = 4 * p;
            TRYPUSH(k.x, p0,     Te);
            TRYPUSH(k.y, p0 + 1, Te);
            TRYPUSH(k.z, p0 + 2, Te);
            TRYPUSH(k.w, p0 + 3, Te);
        }
        __syncthreads();
        M = s_cnt;
        if (M > CAP) {   // boundary bin too fat: refine globally to 21 bits
            for (int i = tid; i < 2048; i += NT) s_hist[i] = 0;
            __syncthreads();
            for (int p = tid; p < PNUM; p += NT) {
                uint32_t k = keys[p];
                if ((k >> 21) == bbe) atomicAdd(&s_hist[(k >> 10) & 0x7FFu], 1u);
            }
            __syncthreads();
            {
                uint32_t cs = 0;
#pragma unroll
                for (int i = 0; i < 8; i++) cs += s_hist[tid * 8 + i];
                s_csum[tid] = cs;
            }
            __syncthreads();
            if (wid == 0) warp_select(s_hist, s_csum, KPRE, n_above, s_sel);
            __syncthreads();
            uint32_t T21 = ((bbe << 11) | s_sel[0]) << 10;
            if (tid == 0) s_cnt = 0;
            __syncthreads();
            for (int p = tid; p < PNUM; p += NT) {
                uint32_t k = keys[p];
                TRYPUSH(k & ~0x3FFu, p, T21);   // compare at 21-bit granularity
            }
            __syncthreads();
            // note: keys pushed with low bits cleared would corrupt scores; redo properly
            if (tid == 0) s_cnt = 0;
            __syncthreads();
            for (int p = tid; p < PNUM; p += NT) {
                uint32_t k = keys[p];
                if ((k >> 10) >= (T21 >> 10)) {
                    uint32_t pos = atomicAdd(&s_cnt, 1u);
                    if (pos < CAP) s_cand[pos] = ((u64)k << 32) | (uint32_t)(~(uint32_t)p);
                }
            }
            __syncthreads();
            M = s_cnt;
            if (M > CAP) M = CAP;
        }
    }
#undef TRYPUSH

    // ============ in-shared refine, 4 levels x 8-bit digits -> exact F ============
    uint32_t pref = 0, n0 = 0;
#pragma unroll
    for (int lev = 0; lev < 4; lev++) {
        const int sh = 24 - lev * 8;
        if (tid < 256) s_hist[tid] = 0;
        __syncthreads();
        for (uint32_t i = tid; i < M; i += NT) {
            uint32_t k = (uint32_t)(s_cand[i] >> 32);
            bool match = (lev == 0) || ((k >> (sh + 8)) == pref);
            if (match) atomicAdd(&s_hist[(k >> sh) & 255u], 1u);
        }
        __syncthreads();
        if (wid == 0) warp_select256(s_hist, KPRE, n0, s_sel);
        __syncthreads();
        pref = (pref << 8) | s_sel[0];
        n0 = s_sel[1];
        __syncthreads();
    }
    const uint32_t F = pref;

    // ================= compact qualifying (key >= F) =================
    if (tid == 0) s_cnt = 0;
    __syncthreads();
    for (uint32_t i = tid; i < M; i += NT) {
        u64 c = s_cand[i];
        if ((uint32_t)(c >> 32) >= F) {
            uint32_t pos = atomicAdd(&s_cnt, 1u);
            if (pos < QCAP) s_h64[pos] = c;
        }
    }
    __syncthreads();
    uint32_t M2 = s_cnt; if (M2 > QCAP) M2 = QCAP;

    // ================= sort: bitonic-256 (generic) or rank-sort (ties) =================
    if (M2 == KPRE) {
        u64 mine = s_h64[tid];
        __syncthreads();
#pragma unroll
        for (uint32_t k = 2; k <= 256; k <<= 1) {
            for (uint32_t j = k >> 1; j >= 1; j >>= 1) {
                u64 other;
                if (j >= 32) {
                    s_key[tid] = mine;
                    __syncthreads();
                    other = s_key[tid ^ j];
                    __syncthreads();
                } else {
                    other = __shfl_xor_sync(0xFFFFFFFFu, mine, j);
                }
                bool lower   = (tid & j) == 0;
                bool dirDesc = (tid & k) == 0;
                bool takeMax = (lower == dirDesc);
                u64 mx = mine > other ? mine : other;
                u64 mn = mine > other ? other : mine;
                mine = takeMax ? mx : mn;
            }
        }
        s_key[tid] = mine;
    } else {
        for (uint32_t i = tid; i < M2; i += NT) {
            u64 mine = s_h64[i];
            uint32_t rank = 0;
            for (uint32_t j = 0; j < M2; j++) rank += (s_h64[j] > mine);
            if (rank < KPRE) s_key[rank] = mine;
        }
    }
    __syncthreads();

    // ======== extract top-256: decode box on demand (exact prep arithmetic) ========
    u64 key = s_key[tid];
    uint32_t idx = ~(uint32_t)key;
    float scv = unmono((uint32_t)(key >> 32));
    float4 bj;
    {
        float4 l  = __ldg((const float4*)loc + (size_t)b * PNUM + idx);
        float4 pr = __ldg((const float4*)prior + idx);
        float cx = pr.x + (l.x * 0.1f) * pr.z;
        float cy = pr.y + (l.y * 0.1f) * pr.w;
        float w  = pr.z * expf(l.z * 0.2f);
        float h  = pr.w * expf(l.w * 0.2f);
        float x1 = cx - w * 0.5f;
        float y1 = cy - h * 0.5f;
        bj = make_float4(x1, y1, x1 + w, y1 + h);
    }
    float aj = fmaxf(bj.z - bj.x, 0.f) * fmaxf(bj.w - bj.y, 0.f);
    s_box[tid]  = bj;
    s_area[tid] = aj;
    {
        bool valid = scv > 0.01f;
        uint32_t bal = __ballot_sync(0xFFFFFFFFu, valid);
        if (lane == 0) s_keep[wid] = bal;
    }
    if (tid < 8) s_rowmask[tid] = 0;
    float* op = out + (size_t)pair * (TOPK * 5);
    {   // float4 zeroing (TOPK*5*4 bytes = 4000, 16B-aligned)
        float4* op4 = (float4*)op;
        if (tid < TOPK * 5 / 4) op4[tid] = make_float4(0.f, 0.f, 0.f, 0.f);
    }
    uint32_t* s_supp = (uint32_t*)s_h64;
    __syncthreads();

    // ===== suppression bitmatrix: balanced schedule, FFMA-band IoU, split diagonal =====
    // iou > 0.45  <=>  inter > (0.45/1.45)*(ai+ag); certified band, exact-div inside band.
#pragma unroll 1
    for (int g = 0; g < 8; g++) {
        const int    colg = g * 32 + lane;
        const float4 bg   = s_box[colg];
        const float  ag   = s_area[colg];
        const float  chi  = __fmul_rn(0.310395f, ag);
        const float  clo  = __fmul_rn(0.310295f, ag);
        const int    gbase = g * 32;
        // main rows: i < 32g -> every colg > i (no lane test)
#pragma unroll 1
        for (int i = wid; i < gbase; i += 8) {
            float4 bi = s_box[i];
            float wx = fmaxf(fminf(bi.z, bg.z) - fmaxf(bi.x, bg.x), 0.f);
            float wy = fmaxf(fminf(bi.w, bg.w) - fmaxf(bi.y, bg.y), 0.f);
            float inter = __fmul_rn(wx, wy);
            float ai = s_area[i];
            bool sup = inter > __fmaf_rn(0.310395f, ai, chi);
            if (!sup && inter >= __fmaf_rn(0.310295f, ai, clo)) {
                float s  = __fadd_rn(ai, ag);
                float ut = fmaxf(__fadd_rn(s, -inter), 1e-9f);
                sup = (inter / ut) > 0.45f;           // exact IEEE path (rare)
            }
            uint32_t bal = __ballot_sync(0xFFFFFFFFu, sup);
            if (lane == 0) {
                s_supp[i * 8 + g] = bal;
                if (bal) atomicOr(&s_rowmask[i >> 5], 1u << (i & 31));
            }
        }
        // diagonal rows: i in [32g, 32g+32) -> lane test needed
#pragma unroll
        for (int t = 0; t < 4; t++) {
            const int i = gbase + wid + t * 8;
            float4 bi = s_box[i];
            float wx = fmaxf(fminf(bi.z, bg.z) - fmaxf(bi.x, bg.x), 0.f);
            float wy = fmaxf(fminf(bi.w, bg.w) - fmaxf(bi.y, bg.y), 0.f);
            float inter = __fmul_rn(wx, wy);
            float ai = s_area[i];
            bool gt  = colg > i;
            bool sup = gt && (inter > __fmaf_rn(0.310395f, ai, chi));
            if (gt && !sup && inter >= __fmaf_rn(0.310295f, ai, clo)) {
                float s  = __fadd_rn(ai, ag);
                float ut = fmaxf(__fadd_rn(s, -inter), 1e-9f);
                sup = (inter / ut) > 0.45f;
            }
            uint32_t bal = __ballot_sync(0xFFFFFFFFu, sup);
            if (lane == 0) {
                s_supp[i * 8 + g] = bal;
                if (bal) atomicOr(&s_rowmask[i >> 5], 1u << (i & 31));
            }
        }
    }
    __syncthreads();

    // ====== sparse greedy scan on warp 0 (only rows that suppress someone) ======
    if (wid == 0) {
        uint32_t kw = (lane < 8) ? s_keep[lane] : 0u;
        for (int w8 = 0; w8 < 8; w8++) {
            uint32_t rm = s_rowmask[w8];
            while (rm) {
                int bit = __ffs(rm) - 1; rm &= rm - 1;
                int i = w8 * 32 + bit;
                uint32_t w = __shfl_sync(0xFFFFFFFFu, kw, w8);
                uint32_t cur = (lane < 8 && lane >= w8) ? s_supp[i * 8 + lane] : 0u;
                if ((w >> bit) & 1u)
                    kw &= ~cur;
            }
        }
        if (lane < 8) s_keep[lane] = kw;
    }
    __syncthreads();

    // ================= compaction + output =================
    if (tid == 0) {
        uint32_t a = 0;
#pragma unroll
        for (int w2 = 0; w2 < 8; w2++) { s_wpre[w2] = a; a += __popc(s_keep[w2]); }
    }
    __syncthreads();

    uint32_t kwm = s_keep[wid];
    if ((kwm >> lane) & 1u) {
        uint32_t rank = s_wpre[wid] + __popc(kwm & ((1u << lane) - 1u));
        if (rank < TOPK) {
            float* r = op + (size_t)rank * 5;
            r[0] = scv;
            r[1] = bj.x; r[2] = bj.y; r[3] = bj.z; r[4] = bj.w;
        }
    }
}

// ------------------------------------------------------------------
extern "C" void kernel_launch(void* const* d_in, const int* in_sizes, int n_in,
                              void* d_out, int out_size) {
    const float* loc   = (const float*)d_in[0];
    const float* conf  = (const float*)d_in[1];
    const float* prior = (const float*)d_in[2];
    float* out = (float*)d_out;

    int total = BNUM * PNUM;
    prep_kernel<<<(total + 255) / 256, 256>>>(conf);
    topk_nms_kernel<<<NPAIR, NT>>>(out, loc, prior);
}

// round 11
// speedup vs baseline: 1.5205x; 1.0268x over previous
#include <cuda_runtime.h>
#include <stdint.h>

#define BNUM 32
#define PNUM 8732
#define CFG  20
#define NPAIR (BNUM*CFG)
#define KPRE 256
#define TOPK 200
#define CAP  2048
#define QCAP 1024
#define NT   256
#define TSAMP 128

typedef unsigned long long u64;

// ------------------------------------------------------------------
__device__ uint32_t g_keys[(size_t)NPAIR * PNUM];   // mono(prob) per [b][c][p]

__device__ __forceinline__ uint32_t mono(float f) {
    uint32_t u = __float_as_uint(f);
    return (u & 0x80000000u) ? ~u : (u | 0x80000000u);
}
__device__ __forceinline__ float unmono(uint32_t k) {
    uint32_t u = (k & 0x80000000u) ? (k ^ 0x80000000u) : ~k;
    return __uint_as_float(u);
}

// ------------------------------------------------------------------
// kernel 1: softmax only (exact jax.nn.softmax order) -> mono keys
// ------------------------------------------------------------------
__global__ void prep_kernel(const float* __restrict__ conf) {
    int g = blockIdx.x * blockDim.x + threadIdx.x;
    if (g >= BNUM * PNUM) return;
    int b = g / PNUM, p = g % PNUM;

    const float* cp = conf + (size_t)g * 21;
    float x[21];
#pragma unroll
    for (int c = 0; c < 21; c++) x[c] = cp[c];
    float m = x[0];
#pragma unroll
    for (int c = 1; c < 21; c++) m = fmaxf(m, x[c]);
    float e[21];
    float s = 0.f;
#pragma unroll
    for (int c = 0; c < 21; c++) { e[c] = expf(x[c] - m); s += e[c]; }
#pragma unroll
    for (int c = 1; c < 21; c++)
        g_keys[((size_t)b * CFG + (c - 1)) * PNUM + p] = mono(e[c] / s);
}

// ------------------------------------------------------------------
// warp 0 helpers (called by all 32 lanes of warp 0)
// ------------------------------------------------------------------
__device__ __forceinline__ void warp_select(const uint32_t* s_hist,
                                            const uint32_t* s_csum,
                                            uint32_t target, uint32_t n0,
                                            volatile uint32_t* s_sel) {
    const int l = threadIdx.x;
    uint32_t v[8]; uint32_t tot = 0;
#pragma unroll
    for (int m = 0; m < 8; m++) { v[m] = s_csum[l * 8 + m]; tot += v[m]; }
    uint32_t incl = tot;
#pragma unroll
    for (int o = 1; o < 32; o <<= 1) {
        uint32_t t = __shfl_down_sync(0xFFFFFFFFu, incl, o);
        if (l + o < 32) incl += t;
    }
    uint32_t above = incl - tot;
    if ((above + n0 < target) && (incl + n0 >= target)) {
        uint32_t acc = above + n0;
        int mm = 0;
        for (int m = 7; m >= 0; m--) {
            if (acc + v[m] >= target) { mm = m; break; }
            acc += v[m];
        }
        int chunk = l * 8 + mm;
        int bb = chunk * 8;
        for (int bi = chunk * 8 + 7; bi >= chunk * 8; bi--) {
            uint32_t h = s_hist[bi];
            if (acc + h >= target) { bb = bi; break; }
            acc += h;
        }
        s_sel[0] = (uint32_t)bb; s_sel[1] = acc;
    }
}

__device__ __forceinline__ void warp_select256(const uint32_t* s_hist,
                                               uint32_t target, uint32_t n0,
                                               volatile uint32_t* s_sel) {
    const int l = threadIdx.x;
    uint32_t v[8]; uint32_t tot = 0;
#pragma unroll
    for (int m = 0; m < 8; m++) { v[m] = s_hist[l * 8 + m]; tot += v[m]; }
    uint32_t incl = tot;
#pragma unroll
    for (int o = 1; o < 32; o <<= 1) {
        uint32_t t = __shfl_down_sync(0xFFFFFFFFu, incl, o);
        if (l + o < 32) incl += t;
    }
    uint32_t above = incl - tot;
    if ((above + n0 < target) && (incl + n0 >= target)) {
        uint32_t acc = above + n0;
        int bb = l * 8;
        for (int m = 7; m >= 0; m--) {
            if (acc + v[m] >= target) { bb = l * 8 + m; break; }
            acc += v[m];
        }
        s_sel[0] = (uint32_t)bb; s_sel[1] = acc;
    }
}

// ------------------------------------------------------------------
// kernel 2: per (b,c) pair
// ------------------------------------------------------------------
__global__ __launch_bounds__(NT) void topk_nms_kernel(float* __restrict__ out,
                                                      const float* __restrict__ loc,
                                                      const float* __restrict__ prior) {
    __shared__ u64                s_h64[1024];     // hist(2048 u32) / compacted / supp matrix
    __shared__ uint32_t           s_csum[256];
    __shared__ u64                s_cand[CAP];
    __shared__ u64                s_key[KPRE];
    __shared__ float4             s_box[KPRE];
    __shared__ float              s_area[KPRE];
    __shared__ uint32_t           s_keep[8];
    __shared__ uint32_t           s_wpre[8];
    __shared__ uint32_t           s_rowmask[8];
    __shared__ uint32_t           s_sel[2];
    __shared__ uint32_t           s_cnt;
    uint32_t* s_hist = (uint32_t*)s_h64;

    const int pair = blockIdx.x;
    const int b    = pair / CFG;
    const int tid  = threadIdx.x;
    const int wid  = tid >> 5, lane = tid & 31;
    const uint32_t* __restrict__ keys = g_keys + (size_t)pair * PNUM;
    const uint4* __restrict__ keys4 = (const uint4*)keys;
    const int N4 = PNUM / 4;  // 2183

    // ================= sample histogram (25% stride sample, 2184 keys) =================
    {   // vectorized zeroing: 2048 u32 = 512 uint4
        uint4* hz = (uint4*)s_hist;
        hz[tid] = make_uint4(0, 0, 0, 0);
        hz[tid + 256] = make_uint4(0, 0, 0, 0);
    }
    __syncthreads();
    for (int i = tid; i < 546; i += NT) {
        uint4 k = keys4[i * 4];
        atomicAdd(&s_hist[k.x >> 21], 1u);
        atomicAdd(&s_hist[k.y >> 21], 1u);
        atomicAdd(&s_hist[k.z >> 21], 1u);
        atomicAdd(&s_hist[k.w >> 21], 1u);
    }
    __syncthreads();
    {
        uint32_t cs = 0;
#pragma unroll
        for (int i = 0; i < 8; i++) cs += s_hist[tid * 8 + i];
        s_csum[tid] = cs;
    }
    __syncthreads();
    if (wid == 0) warp_select(s_hist, s_csum, TSAMP, 0, s_sel);
    __syncthreads();
    const uint32_t T0 = s_sel[0] << 21;      // direct 32-bit threshold

    // ============ gather: key >= T0 (per-lane atomics, unroll-2 for MLP) ============
    if (tid == 0) s_cnt = 0;
    __syncthreads();
#define TRYPUSH(kk, pp, TH) \
    if ((kk) >= (TH)) { \
        uint32_t pos = atomicAdd(&s_cnt, 1u); \
        if (pos < CAP) s_cand[pos] = ((u64)(kk) << 32) | (uint32_t)(~(uint32_t)(pp)); }
#define PUSH4(k, p0, TH) \
    TRYPUSH((k).x, (p0), TH); TRYPUSH((k).y, (p0) + 1, TH); \
    TRYPUSH((k).z, (p0) + 2, TH); TRYPUSH((k).w, (p0) + 3, TH);
    {
        int p = tid;
        for (; p + NT < N4; p += 2 * NT) {
            uint4 ka = keys4[p];
            uint4 kb = keys4[p + NT];
            PUSH4(ka, 4 * p, T0);
            PUSH4(kb, 4 * (p + NT), T0);
        }
        for (; p < N4; p += NT) {
            uint4 k = keys4[p];
            PUSH4(k, 4 * p, T0);
        }
    }
    __syncthreads();
    uint32_t M = s_cnt;

    // ================= fallback: exact global select (rare) =================
    if (M < KPRE || M > CAP) {
        for (int i = tid; i < 2048; i += NT) s_hist[i] = 0;
        __syncthreads();
        for (int p = tid; p < N4; p += NT) {
            uint4 k = keys4[p];
            atomicAdd(&s_hist[k.x >> 21], 1u);
            atomicAdd(&s_hist[k.y >> 21], 1u);
            atomicAdd(&s_hist[k.z >> 21], 1u);
            atomicAdd(&s_hist[k.w >> 21], 1u);
        }
        __syncthreads();
        {
            uint32_t cs = 0;
#pragma unroll
            for (int i = 0; i < 8; i++) cs += s_hist[tid * 8 + i];
            s_csum[tid] = cs;
        }
        __syncthreads();
        if (wid == 0) warp_select(s_hist, s_csum, KPRE, 0, s_sel);
        __syncthreads();
        uint32_t bbe = s_sel[0], n_above = s_sel[1];
        uint32_t Te = bbe << 21;
        if (tid == 0) s_cnt = 0;
        __syncthreads();
        for (int p = tid; p < N4; p += NT) {
            uint4 k = keys4[p];
            PUSH4(k, 4 * p, Te);
        }
        __syncthreads();
        M = s_cnt;
        if (M > CAP) {   // boundary bin too fat: refine globally to 21 bits
            for (int i = tid; i < 2048; i += NT) s_hist[i] = 0;
            __syncthreads();
            for (int p = tid; p < PNUM; p += NT) {
                uint32_t k = keys[p];
                if ((k >> 21) == bbe) atomicAdd(&s_hist[(k >> 10) & 0x7FFu], 1u);
            }
            __syncthreads();
            {
                uint32_t cs = 0;
#pragma unroll
                for (int i = 0; i < 8; i++) cs += s_hist[tid * 8 + i];
                s_csum[tid] = cs;
            }
            __syncthreads();
            if (wid == 0) warp_select(s_hist, s_csum, KPRE, n_above, s_sel);
            __syncthreads();
            uint32_t pref21 = (bbe << 11) | s_sel[0];
            if (tid == 0) s_cnt = 0;
            __syncthreads();
            for (int p = tid; p < PNUM; p += NT) {
                uint32_t k = keys[p];
                if ((k >> 10) >= pref21) {
                    uint32_t pos = atomicAdd(&s_cnt, 1u);
                    if (pos < CAP) s_cand[pos] = ((u64)k << 32) | (uint32_t)(~(uint32_t)p);
                }
            }
            __syncthreads();
            M = s_cnt;
            if (M > CAP) M = CAP;
        }
    }
#undef PUSH4
#undef TRYPUSH

    // ============ in-shared refine, 4 levels x 8-bit digits -> exact F ============
    uint32_t pref = 0, n0 = 0;
#pragma unroll
    for (int lev = 0; lev < 4; lev++) {
        const int sh = 24 - lev * 8;
        if (tid < 256) s_hist[tid] = 0;
        __syncthreads();
        for (uint32_t i = tid; i < M; i += NT) {
            uint32_t k = (uint32_t)(s_cand[i] >> 32);
            bool match = (lev == 0) || ((k >> (sh + 8)) == pref);
            if (match) atomicAdd(&s_hist[(k >> sh) & 255u], 1u);
        }
        __syncthreads();
        if (wid == 0) warp_select256(s_hist, KPRE, n0, s_sel);
        __syncthreads();
        pref = (pref << 8) | s_sel[0];
        n0 = s_sel[1];
        __syncthreads();
    }
    const uint32_t F = pref;

    // ================= compact qualifying (key >= F) =================
    if (tid == 0) s_cnt = 0;
    __syncthreads();
    for (uint32_t i = tid; i < M; i += NT) {
        u64 c = s_cand[i];
        if ((uint32_t)(c >> 32) >= F) {
            uint32_t pos = atomicAdd(&s_cnt, 1u);
            if (pos < QCAP) s_h64[pos] = c;
        }
    }
    __syncthreads();
    uint32_t M2 = s_cnt; if (M2 > QCAP) M2 = QCAP;

    // ================= sort: bitonic-256 (generic) or rank-sort (ties) =================
    if (M2 == KPRE) {
        u64 mine = s_h64[tid];
        __syncthreads();
#pragma unroll
        for (uint32_t k = 2; k <= 256; k <<= 1) {
            for (uint32_t j = k >> 1; j >= 1; j >>= 1) {
                u64 other;
                if (j >= 32) {
                    s_key[tid] = mine;
                    __syncthreads();
                    other = s_key[tid ^ j];
                    __syncthreads();
                } else {
                    other = __shfl_xor_sync(0xFFFFFFFFu, mine, j);
                }
                bool lower   = (tid & j) == 0;
                bool dirDesc = (tid & k) == 0;
                bool takeMax = (lower == dirDesc);
                u64 mx = mine > other ? mine : other;
                u64 mn = mine > other ? other : mine;
                mine = takeMax ? mx : mn;
            }
        }
        s_key[tid] = mine;
    } else {
        for (uint32_t i = tid; i < M2; i += NT) {
            u64 mine = s_h64[i];
            uint32_t rank = 0;
            for (uint32_t j = 0; j < M2; j++) rank += (s_h64[j] > mine);
            if (rank < KPRE) s_key[rank] = mine;
        }
    }
    __syncthreads();

    // ======== extract top-256: decode box on demand (exact prep arithmetic) ========
    u64 key = s_key[tid];
    uint32_t idx = ~(uint32_t)key;
    float scv = unmono((uint32_t)(key >> 32));
    float4 bj;
    {
        float4 l  = __ldg((const float4*)loc + (size_t)b * PNUM + idx);
        float4 pr = __ldg((const float4*)prior + idx);
        float cx = pr.x + (l.x * 0.1f) * pr.z;
        float cy = pr.y + (l.y * 0.1f) * pr.w;
        float w  = pr.z * expf(l.z * 0.2f);
        float h  = pr.w * expf(l.w * 0.2f);
        float x1 = cx - w * 0.5f;
        float y1 = cy - h * 0.5f;
        bj = make_float4(x1, y1, x1 + w, y1 + h);
    }
    float aj = fmaxf(bj.z - bj.x, 0.f) * fmaxf(bj.w - bj.y, 0.f);
    s_box[tid]  = bj;
    s_area[tid] = aj;
    {
        bool valid = scv > 0.01f;
        uint32_t bal = __ballot_sync(0xFFFFFFFFu, valid);
        if (lane == 0) s_keep[wid] = bal;
    }
    if (tid < 8) s_rowmask[tid] = 0;
    float* op = out + (size_t)pair * (TOPK * 5);
    {   // float4 zeroing (TOPK*5*4 bytes = 4000, 16B-aligned)
        float4* op4 = (float4*)op;
        if (tid < TOPK * 5 / 4) op4[tid] = make_float4(0.f, 0.f, 0.f, 0.f);
    }
    uint32_t* s_supp = (uint32_t*)s_h64;
    __syncthreads();

    // ===== suppression bitmatrix: balanced schedule, FFMA-band IoU =====
    // main rows unrolled 4-wide (count per (warp,g) is exactly 4g): 4 chains in flight
#pragma unroll 1
    for (int g = 0; g < 8; g++) {
        const int    colg = g * 32 + lane;
        const float4 bg   = s_box[colg];
        const float  ag   = s_area[colg];
        const float  chi  = __fmul_rn(0.310395f, ag);
        const float  clo  = __fmul_rn(0.310295f, ag);
        const int    gbase = g * 32;
        // main rows: i < 32g -> colg > i always (no lane test)
#pragma unroll 1
        for (int t = 0; t < g; t++) {
#pragma unroll
            for (int u = 0; u < 4; u++) {
                const int i = wid + t * 32 + u * 8;
                float4 bi = s_box[i];
                float wx = fmaxf(fminf(bi.z, bg.z) - fmaxf(bi.x, bg.x), 0.f);
                float wy = fmaxf(fminf(bi.w, bg.w) - fmaxf(bi.y, bg.y), 0.f);
                float inter = __fmul_rn(wx, wy);
                float ai = s_area[i];
                bool sup = inter > __fmaf_rn(0.310395f, ai, chi);
                if (!sup && inter >= __fmaf_rn(0.310295f, ai, clo)) {
                    float s  = __fadd_rn(ai, ag);
                    float ut = fmaxf(__fadd_rn(s, -inter), 1e-9f);
                    sup = (inter / ut) > 0.45f;           // exact IEEE path (rare)
                }
                uint32_t bal = __ballot_sync(0xFFFFFFFFu, sup);
                if (lane == 0) {
                    s_supp[i * 8 + g] = bal;
                    if (bal) atomicOr(&s_rowmask[i >> 5], 1u << (i & 31));
                }
            }
        }
        // diagonal rows: i in [32g, 32g+32) -> lane test needed
#pragma unroll
        for (int t = 0; t < 4; t++) {
            const int i = gbase + wid + t * 8;
            float4 bi = s_box[i];
            float wx = fmaxf(fminf(bi.z, bg.z) - fmaxf(bi.x, bg.x), 0.f);
            float wy = fmaxf(fminf(bi.w, bg.w) - fmaxf(bi.y, bg.y), 0.f);
            float inter = __fmul_rn(wx, wy);
            float ai = s_area[i];
            bool gt  = colg > i;
            bool sup = gt && (inter > __fmaf_rn(0.310395f, ai, chi));
            if (gt && !sup && inter >= __fmaf_rn(0.310295f, ai, clo)) {
                float s  = __fadd_rn(ai, ag);
                float ut = fmaxf(__fadd_rn(s, -inter), 1e-9f);
                sup = (inter / ut) > 0.45f;
            }
            uint32_t bal = __ballot_sync(0xFFFFFFFFu, sup);
            if (lane == 0) {
                s_supp[i * 8 + g] = bal;
                if (bal) atomicOr(&s_rowmask[i >> 5], 1u << (i & 31));
            }
        }
    }
    __syncthreads();

    // ====== sparse greedy scan on warp 0 (only rows that suppress someone) ======
    if (wid == 0) {
        uint32_t kw = (lane < 8) ? s_keep[lane] : 0u;
        for (int w8 = 0; w8 < 8; w8++) {
            uint32_t rm = s_rowmask[w8];
            while (rm) {
                int bit = __ffs(rm) - 1; rm &= rm - 1;
                int i = w8 * 32 + bit;
                uint32_t w = __shfl_sync(0xFFFFFFFFu, kw, w8);
                uint32_t cur = (lane < 8 && lane >= w8) ? s_supp[i * 8 + lane] : 0u;
                if ((w >> bit) & 1u)
                    kw &= ~cur;
            }
        }
        if (lane < 8) s_keep[lane] = kw;
    }
    __syncthreads();

    // ================= compaction + output =================
    if (tid == 0) {
        uint32_t a = 0;
#pragma unroll
        for (int w2 = 0; w2 < 8; w2++) { s_wpre[w2] = a; a += __popc(s_keep[w2]); }
    }
    __syncthreads();

    uint32_t kwm = s_keep[wid];
    if ((kwm >> lane) & 1u) {
        uint32_t rank = s_wpre[wid] + __popc(kwm & ((1u << lane) - 1u));
        if (rank < TOPK) {
            float* r = op + (size_t)rank * 5;
            r[0] = scv;
            r[1] = bj.x; r[2] = bj.y; r[3] = bj.z; r[4] = bj.w;
        }
    }
}

// ------------------------------------------------------------------
extern "C" void kernel_launch(void* const* d_in, const int* in_sizes, int n_in,
                              void* d_out, int out_size) {
    const float* loc   = (const float*)d_in[0];
    const float* conf  = (const float*)d_in[1];
    const float* prior = (const float*)d_in[2];
    float* out = (float*)d_out;

    int total = BNUM * PNUM;
    prep_kernel<<<(total + 255) / 256, 256>>>(conf);
    topk_nms_kernel<<<NPAIR, NT>>>(out, loc, prior);
}